// round 6
// baseline (speedup 1.0000x reference)
#include <cuda_runtime.h>
#include <cuda_fp16.h>
#include <cstdint>

#define BB 8
#define NN 1024
#define CC 768
#define HH 12
#define DD 64
#define M_ROWS (BB * NN)        // 8192
#define QKV_COLS (3 * CC)       // 2304
#define ATT_SCALE 0.125f
#define LOG2E 1.4426950408889634f

// Scratch (device globals: allocation-free)
__device__ __half g_x_h[(size_t)M_ROWS * CC];
__device__ __half g_wqkv_t[(size_t)QKV_COLS * CC];   // [2304][768] K-major
__device__ __half g_wproj_t[(size_t)CC * CC];        // [768][768]  K-major
__device__ __half g_qkv_h[(size_t)M_ROWS * QKV_COLS];
__device__ __half g_att_h[(size_t)M_ROWS * CC];

// ---------------------------------------------------------------------------
// PTX helpers
// ---------------------------------------------------------------------------
__device__ __forceinline__ unsigned sptr(const void* p) {
    return (unsigned)__cvta_generic_to_shared(p);
}
__device__ __forceinline__ void cp16(unsigned s, const void* g) {
    asm volatile("cp.async.cg.shared.global [%0], [%1], 16;\n" :: "r"(s), "l"(g));
}
__device__ __forceinline__ void cp_commit() {
    asm volatile("cp.async.commit_group;\n");
}
template <int N>
__device__ __forceinline__ void cp_wait() {
    asm volatile("cp.async.wait_group %0;\n" :: "n"(N));
}
__device__ __forceinline__ void ldsm4(unsigned r[4], unsigned a) {
    asm volatile("ldmatrix.sync.aligned.m8n8.x4.shared.b16 {%0,%1,%2,%3}, [%4];\n"
                 : "=r"(r[0]), "=r"(r[1]), "=r"(r[2]), "=r"(r[3]) : "r"(a));
}
__device__ __forceinline__ void ldsm4t(unsigned r[4], unsigned a) {
    asm volatile("ldmatrix.sync.aligned.m8n8.x4.trans.shared.b16 {%0,%1,%2,%3}, [%4];\n"
                 : "=r"(r[0]), "=r"(r[1]), "=r"(r[2]), "=r"(r[3]) : "r"(a));
}
__device__ __forceinline__ void mma16816(float c[4], const unsigned a[4],
                                         unsigned b0, unsigned b1) {
    asm volatile(
        "mma.sync.aligned.m16n8k16.row.col.f32.f16.f16.f32 "
        "{%0,%1,%2,%3},{%4,%5,%6,%7},{%8,%9},{%0,%1,%2,%3};\n"
        : "+f"(c[0]), "+f"(c[1]), "+f"(c[2]), "+f"(c[3])
        : "r"(a[0]), "r"(a[1]), "r"(a[2]), "r"(a[3]), "r"(b0), "r"(b1));
}
__device__ __forceinline__ unsigned f2h2(float lo, float hi) {
    __half2 h = __floats2half2_rn(lo, hi);
    return *(unsigned*)&h;
}
__device__ __forceinline__ float ex2(float x) {
    float r;
    asm("ex2.approx.f32 %0, %1;" : "=f"(r) : "f"(x));
    return r;
}
__device__ __forceinline__ void store2(__half* p, float x, float y) {
    *(__half2*)p = __floats2half2_rn(x, y);
}
__device__ __forceinline__ void store2(float* p, float x, float y) {
    *(float2*)p = make_float2(x, y);
}

// ---------------------------------------------------------------------------
// conversions
// ---------------------------------------------------------------------------
__global__ void cvt_f32_f16_kernel(const float* __restrict__ in,
                                   __half* __restrict__ out, int n4) {
    int i = blockIdx.x * 256 + threadIdx.x;
    if (i < n4) {
        float4 v = ((const float4*)in)[i];
        __half2 h0 = __floats2half2_rn(v.x, v.y);
        __half2 h1 = __floats2half2_rn(v.z, v.w);
        ((uint2*)out)[i] = make_uint2(*(unsigned*)&h0, *(unsigned*)&h1);
    }
}

__global__ void transpose_cvt_kernel(const float* __restrict__ W,
                                     __half* __restrict__ Wt,
                                     int rows, int cols) {
    __shared__ float t[32][33];
    const int x  = blockIdx.x * 32 + threadIdx.x;
    const int y0 = blockIdx.y * 32 + threadIdx.y;
    #pragma unroll
    for (int i = 0; i < 4; i++)
        t[threadIdx.y + i * 8][threadIdx.x] = W[(size_t)(y0 + i * 8) * cols + x];
    __syncthreads();
    const int xo  = blockIdx.y * 32 + threadIdx.x;
    const int yo0 = blockIdx.x * 32 + threadIdx.y;
    #pragma unroll
    for (int i = 0; i < 4; i++)
        Wt[(size_t)(yo0 + i * 8) * rows + xo] =
            __float2half(t[threadIdx.x][threadIdx.y + i * 8]);
}

// ---------------------------------------------------------------------------
// HMMA GEMM: C[M,N] = A[M,K] @ Bt[N,K]^T + bias.
// CTA tile 128x128, BK=32, 3-stage cp.async pipeline, 256 threads,
// 8 warps (4m x 2n), warp tile 32x64.  2 CTAs/SM (launch_bounds).
// smem rows = 64B (32 halves) = 4 chunks; swizzle c ^= (row>>1)&3.
// ---------------------------------------------------------------------------
template <typename OutT>
__global__ __launch_bounds__(256, 2) void gemm_mma_kernel(
    const __half* __restrict__ A, const __half* __restrict__ Bt,
    const float* __restrict__ bias, OutT* __restrict__ C,
    int M, int Kdim, int Ncols)
{
    constexpr int ASZ   = 128 * 64;              // 8 KB per A stage
    constexpr int STAGE = 2 * ASZ;               // 16 KB

    extern __shared__ char smem[];
    const uint32_t sb = sptr(smem);

    const int tid  = threadIdx.x;
    const int lane = tid & 31;
    const int wid  = tid >> 5;
    const int wm   = wid >> 1;                  // 0..3
    const int wn   = wid & 1;                   // 0..1
    const int r    = lane >> 2;
    const int q    = lane & 3;
    const int mat  = lane >> 3;
    const int mi   = lane & 7;

    const int rowBase = blockIdx.y * 128;
    const int colBase = blockIdx.x * 128;

    float acc[2][8][4];
    #pragma unroll
    for (int mb = 0; mb < 2; mb++)
        #pragma unroll
        for (int nf = 0; nf < 8; nf++)
            #pragma unroll
            for (int c = 0; c < 4; c++) acc[mb][nf][c] = 0.f;

    const int nt = Kdim >> 5;

    // staging: 512 A chunks + 512 B chunks, 4 per thread
    const int srow = tid >> 1;                  // 0..127
    const int sc0  = (tid & 1) * 2;             // 0 or 2

    auto stage = [&](int buf, int k0) {
        const uint32_t base = sb + buf * STAGE;
        #pragma unroll
        for (int c = sc0; c < sc0 + 2; c++) {
            const uint32_t soff = srow * 64 + ((c ^ ((srow >> 1) & 3)) * 16);
            cp16(base + soff,
                 A + (size_t)(rowBase + srow) * Kdim + k0 + c * 8);
            cp16(base + ASZ + soff,
                 Bt + (size_t)(colBase + srow) * Kdim + k0 + c * 8);
        }
        cp_commit();
    };

    stage(0, 0);
    stage(1, 32);

    int buf = 0;
    for (int it = 0; it < nt; it++) {
        if (it + 2 < nt) cp_wait<1>(); else cp_wait<0>();
        __syncthreads();
        if (it + 2 < nt) {
            int nb = buf + 2; if (nb >= 3) nb -= 3;
            stage(nb, (it + 2) * 32);
        }

        const uint32_t bA = sb + buf * STAGE;
        const uint32_t bB = bA + ASZ;

        #pragma unroll
        for (int ks = 0; ks < 2; ks++) {
            const int chb = 2 * ks + (mat >> 1);
            unsigned af[2][4];
            #pragma unroll
            for (int mb = 0; mb < 2; mb++) {
                const int rowA = wm * 32 + mb * 16 + (mat & 1) * 8 + mi;
                ldsm4(af[mb], bA + rowA * 64 + ((chb ^ ((rowA >> 1) & 3)) * 16));
            }
            unsigned bf[4][4];
            #pragma unroll
            for (int np = 0; np < 4; np++) {
                const int rowB = wn * 64 + np * 16 + (mat & 1) * 8 + mi;
                ldsm4(bf[np], bB + rowB * 64 + ((chb ^ ((rowB >> 1) & 3)) * 16));
            }
            #pragma unroll
            for (int mb = 0; mb < 2; mb++)
                #pragma unroll
                for (int nf = 0; nf < 8; nf++)
                    mma16816(acc[mb][nf], af[mb],
                             bf[nf >> 1][nf & 1], bf[nf >> 1][(nf & 1) + 2]);
        }
        if (++buf == 3) buf = 0;
    }

    #pragma unroll
    for (int mb = 0; mb < 2; mb++) {
        const int row0 = rowBase + wm * 32 + mb * 16 + r;
        #pragma unroll
        for (int nf = 0; nf < 8; nf++) {
            const int col = colBase + wn * 64 + nf * 8 + 2 * q;
            const float2 bv = *(const float2*)&bias[col];
            store2(&C[(size_t)row0 * Ncols + col],
                   acc[mb][nf][0] + bv.x, acc[mb][nf][1] + bv.y);
            store2(&C[(size_t)(row0 + 8) * Ncols + col],
                   acc[mb][nf][2] + bv.x, acc[mb][nf][3] + bv.y);
        }
    }
}

#define GEMM_SMEM (3 * 2 * 128 * 64)   // 49152

// ---------------------------------------------------------------------------
// fp16 flash attention. CTA = (b,h, 128 q-rows), 8 warps x 16 rows, 256 thr.
// Skips fully-padded key tiles (exact: exp underflows to 0 in reference).
// Softmax in exp2 domain. K tiles of 64 keys, cp.async double-buffered.
// ---------------------------------------------------------------------------
#define AT_Q  0
#define AT_KV 16384
#define AT_M  49152
#define AT_P  53248
#define AT_SMEM (AT_P + 16)

__global__ __launch_bounds__(256, 2) void attn_f16_kernel(
    const __half* __restrict__ qkv, const float* __restrict__ mask,
    __half* __restrict__ out)
{
    extern __shared__ char smem[];
    const uint32_t sb  = sptr(smem);
    const uint32_t sQ  = sb + AT_Q;
    const uint32_t sKV = sb + AT_KV;
    float* Ms = (float*)(smem + AT_M);
    int* sP   = (int*)(smem + AT_P);

    const int bh = blockIdx.x;
    const int b  = bh / HH;
    const int h  = bh % HH;
    const int qt = blockIdx.y;

    const int tid  = threadIdx.x;
    const int lane = tid & 31;
    const int w    = tid >> 5;
    const int r    = lane >> 2;
    const int q    = lane & 3;
    const int mat  = lane >> 3;
    const int mi   = lane & 7;

    if (tid == 0) *sP = NN;

    // stage Q: 128 rows x 8 chunks
    #pragma unroll
    for (int i = 0; i < 4; i++) {
        const int j = tid + i * 256;
        const int row = j >> 3, c0 = j & 7;
        cp16(sQ + (row * 8 + (c0 ^ (row & 7))) * 16,
             qkv + (size_t)(b * NN + qt * 128 + row) * QKV_COLS + h * DD + c0 * 8);
    }
    cp_commit();

    auto stageKV = [&](int buf, int kt) {
        #pragma unroll
        for (int i = 0; i < 4; i++) {
            const int j  = tid + i * 256;
            const int kv = j >> 9;
            const int jj = j & 511;
            const int row = jj >> 3, c0 = jj & 7;
            cp16(sKV + (buf * 1024 + kv * 512 + row * 8 + (c0 ^ (row & 7))) * 16,
                 qkv + (size_t)(b * NN + kt * 64 + row) * QKV_COLS +
                     (kv + 1) * CC + h * DD + c0 * 8);
        }
        cp_commit();
    };

    stageKV(0, 0);

    // stage mask (pre-multiplied by log2e)
    {
        float4 mv = ((const float4*)(mask + b * NN))[tid];
        mv.x *= LOG2E; mv.y *= LOG2E; mv.z *= LOG2E; mv.w *= LOG2E;
        ((float4*)Ms)[tid] = mv;
    }

    cp_wait<0>();
    __syncthreads();

    // first padded position -> number of key tiles to process
    {
        int firstPad = NN;
        #pragma unroll
        for (int i = 0; i < 4; i++) {
            const int idx = tid * 4 + i;
            if (Ms[idx] < -1e8f) { firstPad = idx; break; }
        }
        if (firstPad < NN) atomicMin(sP, firstPad);
    }
    __syncthreads();
    const int ntk = (*sP + 63) >> 6;

    // Q fragments, persistent
    unsigned qf[4][4];
    #pragma unroll
    for (int ks = 0; ks < 4; ks++) {
        const int rowQ = w * 16 + (mat & 1) * 8 + mi;
        const int ch   = 2 * ks + (mat >> 1);
        ldsm4(qf[ks], sQ + (rowQ * 8 + (ch ^ (rowQ & 7))) * 16);
    }

    float o[8][4];
    #pragma unroll
    for (int nf = 0; nf < 8; nf++)
        #pragma unroll
        for (int c = 0; c < 4; c++) o[nf][c] = 0.f;
    float m0 = -1e30f, m1 = -1e30f, l0 = 0.f, l1 = 0.f;

    const float SC2 = ATT_SCALE * LOG2E;

    for (int kt = 0; kt < ntk; kt++) {
        if (kt + 1 < ntk) { stageKV((kt + 1) & 1, kt + 1); cp_wait<1>(); }
        else              { cp_wait<0>(); }
        __syncthreads();

        const uint32_t sK = sKV + (kt & 1) * 1024 * 16;
        const uint32_t sV = sK + 512 * 16;

        // ---- S = Q K^T ----
        float s[8][4];
        #pragma unroll
        for (int nf = 0; nf < 8; nf++)
            #pragma unroll
            for (int c = 0; c < 4; c++) s[nf][c] = 0.f;

        #pragma unroll
        for (int ks = 0; ks < 4; ks++) {
            unsigned bk[4][4];
            #pragma unroll
            for (int np = 0; np < 4; np++) {
                const int rowK = np * 16 + (mat & 1) * 8 + mi;
                const int ch   = 2 * ks + (mat >> 1);
                ldsm4(bk[np], sK + (rowK * 8 + (ch ^ (rowK & 7))) * 16);
            }
            #pragma unroll
            for (int nf = 0; nf < 8; nf++)
                mma16816(s[nf], qf[ks],
                         bk[nf >> 1][nf & 1], bk[nf >> 1][(nf & 1) + 2]);
        }

        // ---- scale + mask (exp2 domain) + online softmax ----
        float tmax0 = -1e30f, tmax1 = -1e30f;
        #pragma unroll
        for (int nf = 0; nf < 8; nf++) {
            const int col = kt * 64 + nf * 8 + 2 * q;
            const float2 mv = *(const float2*)&Ms[col];
            s[nf][0] = s[nf][0] * SC2 + mv.x;
            s[nf][1] = s[nf][1] * SC2 + mv.y;
            s[nf][2] = s[nf][2] * SC2 + mv.x;
            s[nf][3] = s[nf][3] * SC2 + mv.y;
            tmax0 = fmaxf(tmax0, fmaxf(s[nf][0], s[nf][1]));
            tmax1 = fmaxf(tmax1, fmaxf(s[nf][2], s[nf][3]));
        }
        #pragma unroll
        for (int off = 1; off <= 2; off <<= 1) {
            tmax0 = fmaxf(tmax0, __shfl_xor_sync(0xffffffffu, tmax0, off));
            tmax1 = fmaxf(tmax1, __shfl_xor_sync(0xffffffffu, tmax1, off));
        }
        const float nm0 = fmaxf(m0, tmax0);
        const float nm1 = fmaxf(m1, tmax1);
        const float cr0 = ex2(m0 - nm0);
        const float cr1 = ex2(m1 - nm1);
        l0 *= cr0; l1 *= cr1;
        #pragma unroll
        for (int nf = 0; nf < 8; nf++) {
            o[nf][0] *= cr0; o[nf][1] *= cr0;
            o[nf][2] *= cr1; o[nf][3] *= cr1;
        }
        m0 = nm0; m1 = nm1;

        #pragma unroll
        for (int nf = 0; nf < 8; nf++) {
            s[nf][0] = ex2(s[nf][0] - nm0);
            s[nf][1] = ex2(s[nf][1] - nm0);
            s[nf][2] = ex2(s[nf][2] - nm1);
            s[nf][3] = ex2(s[nf][3] - nm1);
            l0 += s[nf][0] + s[nf][1];
            l1 += s[nf][2] + s[nf][3];
        }

        // ---- P fragments in registers ----
        unsigned ap[4][4];
        #pragma unroll
        for (int ks = 0; ks < 4; ks++) {
            ap[ks][0] = f2h2(s[2 * ks][0],     s[2 * ks][1]);
            ap[ks][1] = f2h2(s[2 * ks][2],     s[2 * ks][3]);
            ap[ks][2] = f2h2(s[2 * ks + 1][0], s[2 * ks + 1][1]);
            ap[ks][3] = f2h2(s[2 * ks + 1][2], s[2 * ks + 1][3]);
        }

        // ---- O += P V ----
        #pragma unroll
        for (int ks = 0; ks < 4; ks++) {
            unsigned bv[4][4];
            #pragma unroll
            for (int np = 0; np < 4; np++) {
                const int rowV = ks * 16 + (mat & 1) * 8 + mi;
                const int ch   = 2 * np + (mat >> 1);
                ldsm4t(bv[np], sV + (rowV * 8 + (ch ^ (rowV & 7))) * 16);
            }
            #pragma unroll
            for (int nf = 0; nf < 8; nf++)
                mma16816(o[nf], ap[ks],
                         bv[nf >> 1][(nf & 1) * 2], bv[nf >> 1][(nf & 1) * 2 + 1]);
        }
        __syncthreads();
    }

    // ---- finalize ----
    #pragma unroll
    for (int off = 1; off <= 2; off <<= 1) {
        l0 += __shfl_xor_sync(0xffffffffu, l0, off);
        l1 += __shfl_xor_sync(0xffffffffu, l1, off);
    }
    const float inv0 = 1.f / l0;
    const float inv1 = 1.f / l1;

    const int row0 = b * NN + qt * 128 + w * 16 + r;
    #pragma unroll
    for (int nf = 0; nf < 8; nf++) {
        const int col = h * DD + nf * 8 + 2 * q;
        *(__half2*)&out[(size_t)row0 * CC + col] =
            __floats2half2_rn(o[nf][0] * inv0, o[nf][1] * inv0);
        *(__half2*)&out[(size_t)(row0 + 8) * CC + col] =
            __floats2half2_rn(o[nf][2] * inv1, o[nf][3] * inv1);
    }
}

// ---------------------------------------------------------------------------
// Launch
// ---------------------------------------------------------------------------
extern "C" void kernel_launch(void* const* d_in, const int* in_sizes, int n_in,
                              void* d_out, int out_size)
{
    const float* x      = (const float*)d_in[0];
    const float* amask  = (const float*)d_in[1];
    const float* W_qkv  = (const float*)d_in[2];
    const float* b_qkv  = (const float*)d_in[3];
    const float* W_proj = (const float*)d_in[4];
    const float* b_proj = (const float*)d_in[5];
    float* out = (float*)d_out;

    __half *x_h, *wqkv_t, *wproj_t, *qkv_h, *att_h;
    cudaGetSymbolAddress((void**)&x_h,     g_x_h);
    cudaGetSymbolAddress((void**)&wqkv_t,  g_wqkv_t);
    cudaGetSymbolAddress((void**)&wproj_t, g_wproj_t);
    cudaGetSymbolAddress((void**)&qkv_h,   g_qkv_h);
    cudaGetSymbolAddress((void**)&att_h,   g_att_h);

    static bool attr_set = false;
    if (!attr_set) {
        cudaFuncSetAttribute(gemm_mma_kernel<__half>,
                             cudaFuncAttributeMaxDynamicSharedMemorySize, GEMM_SMEM);
        cudaFuncSetAttribute(gemm_mma_kernel<float>,
                             cudaFuncAttributeMaxDynamicSharedMemorySize, GEMM_SMEM);
        cudaFuncSetAttribute(attn_f16_kernel,
                             cudaFuncAttributeMaxDynamicSharedMemorySize, AT_SMEM);
        attr_set = true;
    }

    // 0) conversions
    {
        const int n4 = M_ROWS * CC / 4;
        cvt_f32_f16_kernel<<<(n4 + 255) / 256, 256>>>(x, x_h, n4);
        transpose_cvt_kernel<<<dim3(QKV_COLS / 32, CC / 32), dim3(32, 8)>>>(
            W_qkv, wqkv_t, CC, QKV_COLS);
        transpose_cvt_kernel<<<dim3(CC / 32, CC / 32), dim3(32, 8)>>>(
            W_proj, wproj_t, CC, CC);
    }
    // 1) QKV projection (fp16 out), 128x128 tiles
    {
        dim3 grid(QKV_COLS / 128, M_ROWS / 128);
        gemm_mma_kernel<__half><<<grid, 256, GEMM_SMEM>>>(
            x_h, wqkv_t, b_qkv, qkv_h, M_ROWS, CC, QKV_COLS);
    }
    // 2) Attention (fp16 out)
    {
        dim3 grid(BB * HH, NN / 128);
        attn_f16_kernel<<<grid, 256, AT_SMEM>>>(qkv_h, amask, att_h);
    }
    // 3) Output projection (fp32 out), 128x128 tiles
    {
        dim3 grid(CC / 128, M_ROWS / 128);
        gemm_mma_kernel<float><<<grid, 256, GEMM_SMEM>>>(
            att_h, wproj_t, b_proj, out, M_ROWS, CC, CC);
    }
}

// round 7
// speedup vs baseline: 1.1172x; 1.1172x over previous
#include <cuda_runtime.h>
#include <cuda_fp16.h>
#include <cstdint>

#define BB 8
#define NN 1024
#define CC 768
#define HH 12
#define DD 64
#define M_ROWS (BB * NN)        // 8192
#define QKV_COLS (3 * CC)       // 2304
#define ATT_SCALE 0.125f
#define LOG2E 1.4426950408889634f

// Scratch (device globals: allocation-free)
__device__ __half g_x_h[(size_t)M_ROWS * CC];
__device__ __half g_wqkv_t[(size_t)QKV_COLS * CC];   // [2304][768] K-major
__device__ __half g_wproj_t[(size_t)CC * CC];        // [768][768]  K-major
__device__ __half g_qkv_h[(size_t)M_ROWS * QKV_COLS];
__device__ __half g_att_h[(size_t)M_ROWS * CC];

// ---------------------------------------------------------------------------
// PTX helpers
// ---------------------------------------------------------------------------
__device__ __forceinline__ unsigned sptr(const void* p) {
    return (unsigned)__cvta_generic_to_shared(p);
}
__device__ __forceinline__ void cp16(unsigned s, const void* g) {
    asm volatile("cp.async.cg.shared.global [%0], [%1], 16;\n" :: "r"(s), "l"(g));
}
__device__ __forceinline__ void cp_commit() {
    asm volatile("cp.async.commit_group;\n");
}
template <int N>
__device__ __forceinline__ void cp_wait() {
    asm volatile("cp.async.wait_group %0;\n" :: "n"(N));
}
__device__ __forceinline__ void ldsm4(unsigned r[4], unsigned a) {
    asm volatile("ldmatrix.sync.aligned.m8n8.x4.shared.b16 {%0,%1,%2,%3}, [%4];\n"
                 : "=r"(r[0]), "=r"(r[1]), "=r"(r[2]), "=r"(r[3]) : "r"(a));
}
__device__ __forceinline__ void ldsm4t(unsigned r[4], unsigned a) {
    asm volatile("ldmatrix.sync.aligned.m8n8.x4.trans.shared.b16 {%0,%1,%2,%3}, [%4];\n"
                 : "=r"(r[0]), "=r"(r[1]), "=r"(r[2]), "=r"(r[3]) : "r"(a));
}
__device__ __forceinline__ void mma16816(float c[4], const unsigned a[4],
                                         unsigned b0, unsigned b1) {
    asm volatile(
        "mma.sync.aligned.m16n8k16.row.col.f32.f16.f16.f32 "
        "{%0,%1,%2,%3},{%4,%5,%6,%7},{%8,%9},{%0,%1,%2,%3};\n"
        : "+f"(c[0]), "+f"(c[1]), "+f"(c[2]), "+f"(c[3])
        : "r"(a[0]), "r"(a[1]), "r"(a[2]), "r"(a[3]), "r"(b0), "r"(b1));
}
__device__ __forceinline__ unsigned f2h2(float lo, float hi) {
    __half2 h = __floats2half2_rn(lo, hi);
    return *(unsigned*)&h;
}
__device__ __forceinline__ float ex2(float x) {
    float r;
    asm("ex2.approx.f32 %0, %1;" : "=f"(r) : "f"(x));
    return r;
}
__device__ __forceinline__ void store2(__half* p, float x, float y) {
    *(__half2*)p = __floats2half2_rn(x, y);
}
__device__ __forceinline__ void store2(float* p, float x, float y) {
    *(float2*)p = make_float2(x, y);
}

// ---------------------------------------------------------------------------
// conversions
// ---------------------------------------------------------------------------
__global__ void cvt_f32_f16_kernel(const float* __restrict__ in,
                                   __half* __restrict__ out, int n4) {
    int i = blockIdx.x * 256 + threadIdx.x;
    if (i < n4) {
        float4 v = ((const float4*)in)[i];
        __half2 h0 = __floats2half2_rn(v.x, v.y);
        __half2 h1 = __floats2half2_rn(v.z, v.w);
        ((uint2*)out)[i] = make_uint2(*(unsigned*)&h0, *(unsigned*)&h1);
    }
}

__global__ void transpose_cvt_kernel(const float* __restrict__ W,
                                     __half* __restrict__ Wt,
                                     int rows, int cols) {
    __shared__ float t[32][33];
    const int x  = blockIdx.x * 32 + threadIdx.x;
    const int y0 = blockIdx.y * 32 + threadIdx.y;
    #pragma unroll
    for (int i = 0; i < 4; i++)
        t[threadIdx.y + i * 8][threadIdx.x] = W[(size_t)(y0 + i * 8) * cols + x];
    __syncthreads();
    const int xo  = blockIdx.y * 32 + threadIdx.x;
    const int yo0 = blockIdx.x * 32 + threadIdx.y;
    #pragma unroll
    for (int i = 0; i < 4; i++)
        Wt[(size_t)(yo0 + i * 8) * rows + xo] =
            __float2half(t[threadIdx.x][threadIdx.y + i * 8]);
}

// ---------------------------------------------------------------------------
// fp16 tensor-core GEMM (EXACT R2 config — best measured: 99.6us on QKV):
// C[M,N] = A[M,K] @ Bt[N,K]^T + bias. 128x128x32 tiles, 2-stage cp.async,
// 256 threads, 8 warps (4m x 2n), warp tile 32x64.
// smem chunk layout: 16B chunks, 4 per row (64B rows), swizzle c ^= (row>>1)&3.
// ---------------------------------------------------------------------------
template <typename OutT>
__global__ __launch_bounds__(256) void gemm_f16_kernel(
    const __half* __restrict__ A, const __half* __restrict__ Bt,
    const float* __restrict__ bias, OutT* __restrict__ C,
    int M, int Kdim, int Ncols)
{
    __shared__ uint4 As[2][512];   // 128 rows x 4 chunks
    __shared__ uint4 Bs[2][512];

    const int tid  = threadIdx.x;
    const int lane = tid & 31;
    const int wid  = tid >> 5;
    const int wm   = wid >> 1;
    const int wn   = wid & 1;
    const int r    = lane >> 2;
    const int q    = lane & 3;
    const int mat  = lane >> 3;
    const int mi   = lane & 7;

    const int rowBase = blockIdx.y * 128;
    const int colBase = blockIdx.x * 128;

    const unsigned sA0 = sptr(&As[0][0]);
    const unsigned sB0 = sptr(&Bs[0][0]);

    float acc[2][8][4];
    #pragma unroll
    for (int mb = 0; mb < 2; mb++)
        #pragma unroll
        for (int nf = 0; nf < 8; nf++)
            #pragma unroll
            for (int c = 0; c < 4; c++) acc[mb][nf][c] = 0.f;

    const int ntiles = Kdim >> 5;

    const int srow = tid >> 2;          // 0..63
    const int sc0  = tid & 3;

    auto stage = [&](int buf, int k0) {
        #pragma unroll
        for (int i = 0; i < 2; i++) {
            const int row = srow + i * 64;
            const int swz = sc0 ^ ((row >> 1) & 3);
            cp16(sA0 + (buf * 512 + row * 4 + swz) * 16,
                 A + (size_t)(rowBase + row) * Kdim + k0 + sc0 * 8);
            cp16(sB0 + (buf * 512 + row * 4 + swz) * 16,
                 Bt + (size_t)(colBase + row) * Kdim + k0 + sc0 * 8);
        }
        cp_commit();
    };

    stage(0, 0);

    for (int it = 0; it < ntiles; it++) {
        if (it + 1 < ntiles) { stage((it + 1) & 1, (it + 1) * 32); cp_wait<1>(); }
        else                 { cp_wait<0>(); }
        __syncthreads();

        const unsigned sAb = sA0 + (it & 1) * 512 * 16;
        const unsigned sBb = sB0 + (it & 1) * 512 * 16;

        #pragma unroll
        for (int ks = 0; ks < 2; ks++) {
            unsigned af[2][4];
            #pragma unroll
            for (int mb = 0; mb < 2; mb++) {
                const int rowA = wm * 32 + mb * 16 + (mat & 1) * 8 + mi;
                const int ch   = 2 * ks + (mat >> 1);
                ldsm4(af[mb], sAb + (rowA * 4 + (ch ^ ((rowA >> 1) & 3))) * 16);
            }
            unsigned bf[4][4];
            #pragma unroll
            for (int np = 0; np < 4; np++) {
                const int rowB = wn * 64 + np * 16 + (mat & 1) * 8 + mi;
                const int ch   = 2 * ks + (mat >> 1);
                ldsm4(bf[np], sBb + (rowB * 4 + (ch ^ ((rowB >> 1) & 3))) * 16);
            }
            #pragma unroll
            for (int mb = 0; mb < 2; mb++)
                #pragma unroll
                for (int nf = 0; nf < 8; nf++)
                    mma16816(acc[mb][nf], af[mb],
                             bf[nf >> 1][nf & 1], bf[nf >> 1][(nf & 1) + 2]);
        }
        __syncthreads();
    }

    #pragma unroll
    for (int mb = 0; mb < 2; mb++) {
        const int row0 = rowBase + wm * 32 + mb * 16 + r;
        #pragma unroll
        for (int nf = 0; nf < 8; nf++) {
            const int col = colBase + wn * 64 + nf * 8 + 2 * q;
            const float2 bv = *(const float2*)&bias[col];
            store2(&C[(size_t)row0 * Ncols + col],
                   acc[mb][nf][0] + bv.x, acc[mb][nf][1] + bv.y);
            store2(&C[(size_t)(row0 + 8) * Ncols + col],
                   acc[mb][nf][2] + bv.x, acc[mb][nf][3] + bv.y);
        }
    }
}

// ---------------------------------------------------------------------------
// fp16 flash attention (R4/R5 config — best measured).
// CTA = (b,h, 128 q-rows), 8 warps x 16 rows, 256 thr. Skips fully-padded
// key tiles; softmax in exp2 domain; K tiles of 64 keys double-buffered.
// ---------------------------------------------------------------------------
#define AT_Q  0
#define AT_KV 16384
#define AT_M  49152
#define AT_P  53248
#define AT_SMEM (AT_P + 16)

__global__ __launch_bounds__(256, 2) void attn_f16_kernel(
    const __half* __restrict__ qkv, const float* __restrict__ mask,
    __half* __restrict__ out)
{
    extern __shared__ char smem[];
    const uint32_t sb  = sptr(smem);
    const uint32_t sQ  = sb + AT_Q;
    const uint32_t sKV = sb + AT_KV;
    float* Ms = (float*)(smem + AT_M);
    int* sP   = (int*)(smem + AT_P);

    const int bh = blockIdx.x;
    const int b  = bh / HH;
    const int h  = bh % HH;
    const int qt = blockIdx.y;

    const int tid  = threadIdx.x;
    const int lane = tid & 31;
    const int w    = tid >> 5;
    const int r    = lane >> 2;
    const int q    = lane & 3;
    const int mat  = lane >> 3;
    const int mi   = lane & 7;

    if (tid == 0) *sP = NN;

    #pragma unroll
    for (int i = 0; i < 4; i++) {
        const int j = tid + i * 256;
        const int row = j >> 3, c0 = j & 7;
        cp16(sQ + (row * 8 + (c0 ^ (row & 7))) * 16,
             qkv + (size_t)(b * NN + qt * 128 + row) * QKV_COLS + h * DD + c0 * 8);
    }
    cp_commit();

    auto stageKV = [&](int buf, int kt) {
        #pragma unroll
        for (int i = 0; i < 4; i++) {
            const int j  = tid + i * 256;
            const int kv = j >> 9;
            const int jj = j & 511;
            const int row = jj >> 3, c0 = jj & 7;
            cp16(sKV + (buf * 1024 + kv * 512 + row * 8 + (c0 ^ (row & 7))) * 16,
                 qkv + (size_t)(b * NN + kt * 64 + row) * QKV_COLS +
                     (kv + 1) * CC + h * DD + c0 * 8);
        }
        cp_commit();
    };

    stageKV(0, 0);

    {
        float4 mv = ((const float4*)(mask + b * NN))[tid];
        mv.x *= LOG2E; mv.y *= LOG2E; mv.z *= LOG2E; mv.w *= LOG2E;
        ((float4*)Ms)[tid] = mv;
    }

    cp_wait<0>();
    __syncthreads();

    {
        int firstPad = NN;
        #pragma unroll
        for (int i = 0; i < 4; i++) {
            const int idx = tid * 4 + i;
            if (Ms[idx] < -1e8f) { firstPad = idx; break; }
        }
        if (firstPad < NN) atomicMin(sP, firstPad);
    }
    __syncthreads();
    const int ntk = (*sP + 63) >> 6;

    unsigned qf[4][4];
    #pragma unroll
    for (int ks = 0; ks < 4; ks++) {
        const int rowQ = w * 16 + (mat & 1) * 8 + mi;
        const int ch   = 2 * ks + (mat >> 1);
        ldsm4(qf[ks], sQ + (rowQ * 8 + (ch ^ (rowQ & 7))) * 16);
    }

    float o[8][4];
    #pragma unroll
    for (int nf = 0; nf < 8; nf++)
        #pragma unroll
        for (int c = 0; c < 4; c++) o[nf][c] = 0.f;
    float m0 = -1e30f, m1 = -1e30f, l0 = 0.f, l1 = 0.f;

    const float SC2 = ATT_SCALE * LOG2E;

    for (int kt = 0; kt < ntk; kt++) {
        if (kt + 1 < ntk) { stageKV((kt + 1) & 1, kt + 1); cp_wait<1>(); }
        else              { cp_wait<0>(); }
        __syncthreads();

        const uint32_t sK = sKV + (kt & 1) * 1024 * 16;
        const uint32_t sV = sK + 512 * 16;

        float s[8][4];
        #pragma unroll
        for (int nf = 0; nf < 8; nf++)
            #pragma unroll
            for (int c = 0; c < 4; c++) s[nf][c] = 0.f;

        #pragma unroll
        for (int ks = 0; ks < 4; ks++) {
            unsigned bk[4][4];
            #pragma unroll
            for (int np = 0; np < 4; np++) {
                const int rowK = np * 16 + (mat & 1) * 8 + mi;
                const int ch   = 2 * ks + (mat >> 1);
                ldsm4(bk[np], sK + (rowK * 8 + (ch ^ (rowK & 7))) * 16);
            }
            #pragma unroll
            for (int nf = 0; nf < 8; nf++)
                mma16816(s[nf], qf[ks],
                         bk[nf >> 1][nf & 1], bk[nf >> 1][(nf & 1) + 2]);
        }

        float tmax0 = -1e30f, tmax1 = -1e30f;
        #pragma unroll
        for (int nf = 0; nf < 8; nf++) {
            const int col = kt * 64 + nf * 8 + 2 * q;
            const float2 mv = *(const float2*)&Ms[col];
            s[nf][0] = s[nf][0] * SC2 + mv.x;
            s[nf][1] = s[nf][1] * SC2 + mv.y;
            s[nf][2] = s[nf][2] * SC2 + mv.x;
            s[nf][3] = s[nf][3] * SC2 + mv.y;
            tmax0 = fmaxf(tmax0, fmaxf(s[nf][0], s[nf][1]));
            tmax1 = fmaxf(tmax1, fmaxf(s[nf][2], s[nf][3]));
        }
        #pragma unroll
        for (int off = 1; off <= 2; off <<= 1) {
            tmax0 = fmaxf(tmax0, __shfl_xor_sync(0xffffffffu, tmax0, off));
            tmax1 = fmaxf(tmax1, __shfl_xor_sync(0xffffffffu, tmax1, off));
        }
        const float nm0 = fmaxf(m0, tmax0);
        const float nm1 = fmaxf(m1, tmax1);
        const float cr0 = ex2(m0 - nm0);
        const float cr1 = ex2(m1 - nm1);
        l0 *= cr0; l1 *= cr1;
        #pragma unroll
        for (int nf = 0; nf < 8; nf++) {
            o[nf][0] *= cr0; o[nf][1] *= cr0;
            o[nf][2] *= cr1; o[nf][3] *= cr1;
        }
        m0 = nm0; m1 = nm1;

        #pragma unroll
        for (int nf = 0; nf < 8; nf++) {
            s[nf][0] = ex2(s[nf][0] - nm0);
            s[nf][1] = ex2(s[nf][1] - nm0);
            s[nf][2] = ex2(s[nf][2] - nm1);
            s[nf][3] = ex2(s[nf][3] - nm1);
            l0 += s[nf][0] + s[nf][1];
            l1 += s[nf][2] + s[nf][3];
        }

        unsigned ap[4][4];
        #pragma unroll
        for (int ks = 0; ks < 4; ks++) {
            ap[ks][0] = f2h2(s[2 * ks][0],     s[2 * ks][1]);
            ap[ks][1] = f2h2(s[2 * ks][2],     s[2 * ks][3]);
            ap[ks][2] = f2h2(s[2 * ks + 1][0], s[2 * ks + 1][1]);
            ap[ks][3] = f2h2(s[2 * ks + 1][2], s[2 * ks + 1][3]);
        }

        #pragma unroll
        for (int ks = 0; ks < 4; ks++) {
            unsigned bv[4][4];
            #pragma unroll
            for (int np = 0; np < 4; np++) {
                const int rowV = ks * 16 + (mat & 1) * 8 + mi;
                const int ch   = 2 * np + (mat >> 1);
                ldsm4t(bv[np], sV + (rowV * 8 + (ch ^ (rowV & 7))) * 16);
            }
            #pragma unroll
            for (int nf = 0; nf < 8; nf++)
                mma16816(o[nf], ap[ks],
                         bv[nf >> 1][(nf & 1) * 2], bv[nf >> 1][(nf & 1) * 2 + 1]);
        }
        __syncthreads();
    }

    #pragma unroll
    for (int off = 1; off <= 2; off <<= 1) {
        l0 += __shfl_xor_sync(0xffffffffu, l0, off);
        l1 += __shfl_xor_sync(0xffffffffu, l1, off);
    }
    const float inv0 = 1.f / l0;
    const float inv1 = 1.f / l1;

    const int row0 = b * NN + qt * 128 + w * 16 + r;
    #pragma unroll
    for (int nf = 0; nf < 8; nf++) {
        const int col = h * DD + nf * 8 + 2 * q;
        *(__half2*)&out[(size_t)row0 * CC + col] =
            __floats2half2_rn(o[nf][0] * inv0, o[nf][1] * inv0);
        *(__half2*)&out[(size_t)(row0 + 8) * CC + col] =
            __floats2half2_rn(o[nf][2] * inv1, o[nf][3] * inv1);
    }
}

// ---------------------------------------------------------------------------
// Launch
// ---------------------------------------------------------------------------
extern "C" void kernel_launch(void* const* d_in, const int* in_sizes, int n_in,
                              void* d_out, int out_size)
{
    const float* x      = (const float*)d_in[0];
    const float* amask  = (const float*)d_in[1];
    const float* W_qkv  = (const float*)d_in[2];
    const float* b_qkv  = (const float*)d_in[3];
    const float* W_proj = (const float*)d_in[4];
    const float* b_proj = (const float*)d_in[5];
    float* out = (float*)d_out;

    __half *x_h, *wqkv_t, *wproj_t, *qkv_h, *att_h;
    cudaGetSymbolAddress((void**)&x_h,     g_x_h);
    cudaGetSymbolAddress((void**)&wqkv_t,  g_wqkv_t);
    cudaGetSymbolAddress((void**)&wproj_t, g_wproj_t);
    cudaGetSymbolAddress((void**)&qkv_h,   g_qkv_h);
    cudaGetSymbolAddress((void**)&att_h,   g_att_h);

    static bool attr_set = false;
    if (!attr_set) {
        cudaFuncSetAttribute(attn_f16_kernel,
                             cudaFuncAttributeMaxDynamicSharedMemorySize, AT_SMEM);
        attr_set = true;
    }

    // 0) conversions
    {
        const int n4 = M_ROWS * CC / 4;
        cvt_f32_f16_kernel<<<(n4 + 255) / 256, 256>>>(x, x_h, n4);
        transpose_cvt_kernel<<<dim3(QKV_COLS / 32, CC / 32), dim3(32, 8)>>>(
            W_qkv, wqkv_t, CC, QKV_COLS);
        transpose_cvt_kernel<<<dim3(CC / 32, CC / 32), dim3(32, 8)>>>(
            W_proj, wproj_t, CC, CC);
    }
    // 1) QKV projection (fp16 out) — R2 GEMM
    {
        dim3 grid(QKV_COLS / 128, M_ROWS / 128);
        gemm_f16_kernel<__half><<<grid, 256>>>(x_h, wqkv_t, b_qkv, qkv_h,
                                               M_ROWS, CC, QKV_COLS);
    }
    // 2) Attention (fp16 out) — R4/R5 kernel
    {
        dim3 grid(BB * HH, NN / 128);
        attn_f16_kernel<<<grid, 256, AT_SMEM>>>(qkv_h, amask, att_h);
    }
    // 3) Output projection (fp32 out) — R2 GEMM
    {
        dim3 grid(CC / 128, M_ROWS / 128);
        gemm_f16_kernel<float><<<grid, 256>>>(att_h, wproj_t, b_proj, out,
                                              M_ROWS, CC, CC);
    }
}

// round 8
// speedup vs baseline: 1.2015x; 1.0755x over previous
#include <cuda_runtime.h>
#include <cuda_fp16.h>
#include <cstdint>

#define BB 8
#define NN 1024
#define CC 768
#define HH 12
#define DD 64
#define M_ROWS (BB * NN)        // 8192
#define QKV_COLS (3 * CC)       // 2304
#define ATT_SCALE 0.125f
#define LOG2E 1.4426950408889634f

// Scratch (device globals: allocation-free)
__device__ __half g_x_h[(size_t)M_ROWS * CC];
__device__ __half g_wqkv_t[(size_t)QKV_COLS * CC];   // [2304][768] K-major
__device__ __half g_wproj_t[(size_t)CC * CC];        // [768][768]  K-major
__device__ __half g_qkv_h[(size_t)M_ROWS * QKV_COLS];
__device__ __half g_att_h[(size_t)M_ROWS * CC];

// ---------------------------------------------------------------------------
// PTX helpers
// ---------------------------------------------------------------------------
__device__ __forceinline__ unsigned sptr(const void* p) {
    return (unsigned)__cvta_generic_to_shared(p);
}
__device__ __forceinline__ void cp16(unsigned s, const void* g) {
    asm volatile("cp.async.cg.shared.global [%0], [%1], 16;\n" :: "r"(s), "l"(g));
}
__device__ __forceinline__ void cp_commit() {
    asm volatile("cp.async.commit_group;\n");
}
template <int N>
__device__ __forceinline__ void cp_wait() {
    asm volatile("cp.async.wait_group %0;\n" :: "n"(N));
}
__device__ __forceinline__ void ldsm4(unsigned r[4], unsigned a) {
    asm volatile("ldmatrix.sync.aligned.m8n8.x4.shared.b16 {%0,%1,%2,%3}, [%4];\n"
                 : "=r"(r[0]), "=r"(r[1]), "=r"(r[2]), "=r"(r[3]) : "r"(a));
}
__device__ __forceinline__ void ldsm4t(unsigned r[4], unsigned a) {
    asm volatile("ldmatrix.sync.aligned.m8n8.x4.trans.shared.b16 {%0,%1,%2,%3}, [%4];\n"
                 : "=r"(r[0]), "=r"(r[1]), "=r"(r[2]), "=r"(r[3]) : "r"(a));
}
__device__ __forceinline__ void mma16816(float c[4], const unsigned a[4],
                                         unsigned b0, unsigned b1) {
    asm volatile(
        "mma.sync.aligned.m16n8k16.row.col.f32.f16.f16.f32 "
        "{%0,%1,%2,%3},{%4,%5,%6,%7},{%8,%9},{%0,%1,%2,%3};\n"
        : "+f"(c[0]), "+f"(c[1]), "+f"(c[2]), "+f"(c[3])
        : "r"(a[0]), "r"(a[1]), "r"(a[2]), "r"(a[3]), "r"(b0), "r"(b1));
}
__device__ __forceinline__ unsigned f2h2(float lo, float hi) {
    __half2 h = __floats2half2_rn(lo, hi);
    return *(unsigned*)&h;
}
__device__ __forceinline__ float ex2(float x) {
    float r;
    asm("ex2.approx.f32 %0, %1;" : "=f"(r) : "f"(x));
    return r;
}
__device__ __forceinline__ void store2(__half* p, float x, float y) {
    *(__half2*)p = __floats2half2_rn(x, y);
}
__device__ __forceinline__ void store2(float* p, float x, float y) {
    *(float2*)p = make_float2(x, y);
}

// ---------------------------------------------------------------------------
// conversions
// ---------------------------------------------------------------------------
__global__ void cvt_f32_f16_kernel(const float* __restrict__ in,
                                   __half* __restrict__ out, int n4) {
    int i = blockIdx.x * 256 + threadIdx.x;
    if (i < n4) {
        float4 v = ((const float4*)in)[i];
        __half2 h0 = __floats2half2_rn(v.x, v.y);
        __half2 h1 = __floats2half2_rn(v.z, v.w);
        ((uint2*)out)[i] = make_uint2(*(unsigned*)&h0, *(unsigned*)&h1);
    }
}

__global__ void transpose_cvt_kernel(const float* __restrict__ W,
                                     __half* __restrict__ Wt,
                                     int rows, int cols) {
    __shared__ float t[32][33];
    const int x  = blockIdx.x * 32 + threadIdx.x;
    const int y0 = blockIdx.y * 32 + threadIdx.y;
    #pragma unroll
    for (int i = 0; i < 4; i++)
        t[threadIdx.y + i * 8][threadIdx.x] = W[(size_t)(y0 + i * 8) * cols + x];
    __syncthreads();
    const int xo  = blockIdx.y * 32 + threadIdx.x;
    const int yo0 = blockIdx.x * 32 + threadIdx.y;
    #pragma unroll
    for (int i = 0; i < 4; i++)
        Wt[(size_t)(yo0 + i * 8) * rows + xo] =
            __float2half(t[threadIdx.x][threadIdx.y + i * 8]);
}

// ---------------------------------------------------------------------------
// fp16 tensor-core GEMM: C[M,N] = A[M,K] @ Bt[N,K]^T + bias.
// 128x128 CTA tile, BK=64, 2-stage cp.async, 256 threads, 8 warps (4m x 2n),
// warp tile 32x64. Half the barrier frequency of the BK=32 config.
// smem rows: 128B (64 halves) = 8 chunks of 16B; swizzle c ^= row&7.
// ---------------------------------------------------------------------------
#define G_ASZ   16384                 // A bytes per stage (128 x 128B)
#define G_STAGE (2 * G_ASZ)           // 32 KB per stage (A+B)
#define GEMM_SMEM (2 * G_STAGE)       // 64 KB

template <typename OutT>
__global__ __launch_bounds__(256) void gemm_f16_kernel(
    const __half* __restrict__ A, const __half* __restrict__ Bt,
    const float* __restrict__ bias, OutT* __restrict__ C,
    int M, int Kdim, int Ncols)
{
    extern __shared__ char smem[];
    const uint32_t sb = sptr(smem);

    const int tid  = threadIdx.x;
    const int lane = tid & 31;
    const int wid  = tid >> 5;
    const int wm   = wid >> 1;
    const int wn   = wid & 1;
    const int r    = lane >> 2;
    const int q    = lane & 3;
    const int mat  = lane >> 3;
    const int mi   = lane & 7;

    const int rowBase = blockIdx.y * 128;
    const int colBase = blockIdx.x * 128;

    float acc[2][8][4];
    #pragma unroll
    for (int mb = 0; mb < 2; mb++)
        #pragma unroll
        for (int nf = 0; nf < 8; nf++)
            #pragma unroll
            for (int c = 0; c < 4; c++) acc[mb][nf][c] = 0.f;

    const int nt = Kdim >> 6;          // BK=64

    auto stage = [&](int buf, int k0) {
        const uint32_t base = sb + buf * G_STAGE;
        #pragma unroll
        for (int i = 0; i < 4; i++) {
            const int j   = i * 256 + tid;      // 0..1023
            const int row = j >> 3;
            const int c   = j & 7;
            const uint32_t soff = row * 128 + ((c ^ (row & 7)) * 16);
            cp16(base + soff,
                 A + (size_t)(rowBase + row) * Kdim + k0 + c * 8);
            cp16(base + G_ASZ + soff,
                 Bt + (size_t)(colBase + row) * Kdim + k0 + c * 8);
        }
        cp_commit();
    };

    stage(0, 0);

    for (int it = 0; it < nt; it++) {
        if (it + 1 < nt) { stage((it + 1) & 1, (it + 1) * 64); cp_wait<1>(); }
        else             { cp_wait<0>(); }
        __syncthreads();

        const uint32_t bA = sb + (it & 1) * G_STAGE;
        const uint32_t bB = bA + G_ASZ;

        #pragma unroll
        for (int ks = 0; ks < 4; ks++) {
            const int chb = 2 * ks + (mat >> 1);
            unsigned af[2][4];
            #pragma unroll
            for (int mb = 0; mb < 2; mb++) {
                const int rowA = wm * 32 + mb * 16 + (mat & 1) * 8 + mi;
                ldsm4(af[mb], bA + rowA * 128 + ((chb ^ (rowA & 7)) * 16));
            }
            unsigned bf[4][4];
            #pragma unroll
            for (int np = 0; np < 4; np++) {
                const int rowB = wn * 64 + np * 16 + (mat & 1) * 8 + mi;
                ldsm4(bf[np], bB + rowB * 128 + ((chb ^ (rowB & 7)) * 16));
            }
            #pragma unroll
            for (int mb = 0; mb < 2; mb++)
                #pragma unroll
                for (int nf = 0; nf < 8; nf++)
                    mma16816(acc[mb][nf], af[mb],
                             bf[nf >> 1][nf & 1], bf[nf >> 1][(nf & 1) + 2]);
        }
        __syncthreads();
    }

    #pragma unroll
    for (int mb = 0; mb < 2; mb++) {
        const int row0 = rowBase + wm * 32 + mb * 16 + r;
        #pragma unroll
        for (int nf = 0; nf < 8; nf++) {
            const int col = colBase + wn * 64 + nf * 8 + 2 * q;
            const float2 bv = *(const float2*)&bias[col];
            store2(&C[(size_t)row0 * Ncols + col],
                   acc[mb][nf][0] + bv.x, acc[mb][nf][1] + bv.y);
            store2(&C[(size_t)(row0 + 8) * Ncols + col],
                   acc[mb][nf][2] + bv.x, acc[mb][nf][3] + bv.y);
        }
    }
}

// ---------------------------------------------------------------------------
// fp16 flash attention (R6 config — best measured, unchanged).
// ---------------------------------------------------------------------------
#define AT_Q  0
#define AT_KV 16384
#define AT_M  49152
#define AT_P  53248
#define AT_SMEM (AT_P + 16)

__global__ __launch_bounds__(256, 2) void attn_f16_kernel(
    const __half* __restrict__ qkv, const float* __restrict__ mask,
    __half* __restrict__ out)
{
    extern __shared__ char smem[];
    const uint32_t sb  = sptr(smem);
    const uint32_t sQ  = sb + AT_Q;
    const uint32_t sKV = sb + AT_KV;
    float* Ms = (float*)(smem + AT_M);
    int* sP   = (int*)(smem + AT_P);

    const int bh = blockIdx.x;
    const int b  = bh / HH;
    const int h  = bh % HH;
    const int qt = blockIdx.y;

    const int tid  = threadIdx.x;
    const int lane = tid & 31;
    const int w    = tid >> 5;
    const int r    = lane >> 2;
    const int q    = lane & 3;
    const int mat  = lane >> 3;
    const int mi   = lane & 7;

    if (tid == 0) *sP = NN;

    #pragma unroll
    for (int i = 0; i < 4; i++) {
        const int j = tid + i * 256;
        const int row = j >> 3, c0 = j & 7;
        cp16(sQ + (row * 8 + (c0 ^ (row & 7))) * 16,
             qkv + (size_t)(b * NN + qt * 128 + row) * QKV_COLS + h * DD + c0 * 8);
    }
    cp_commit();

    auto stageKV = [&](int buf, int kt) {
        #pragma unroll
        for (int i = 0; i < 4; i++) {
            const int j  = tid + i * 256;
            const int kv = j >> 9;
            const int jj = j & 511;
            const int row = jj >> 3, c0 = jj & 7;
            cp16(sKV + (buf * 1024 + kv * 512 + row * 8 + (c0 ^ (row & 7))) * 16,
                 qkv + (size_t)(b * NN + kt * 64 + row) * QKV_COLS +
                     (kv + 1) * CC + h * DD + c0 * 8);
        }
        cp_commit();
    };

    stageKV(0, 0);

    {
        float4 mv = ((const float4*)(mask + b * NN))[tid];
        mv.x *= LOG2E; mv.y *= LOG2E; mv.z *= LOG2E; mv.w *= LOG2E;
        ((float4*)Ms)[tid] = mv;
    }

    cp_wait<0>();
    __syncthreads();

    {
        int firstPad = NN;
        #pragma unroll
        for (int i = 0; i < 4; i++) {
            const int idx = tid * 4 + i;
            if (Ms[idx] < -1e8f) { firstPad = idx; break; }
        }
        if (firstPad < NN) atomicMin(sP, firstPad);
    }
    __syncthreads();
    const int ntk = (*sP + 63) >> 6;

    unsigned qf[4][4];
    #pragma unroll
    for (int ks = 0; ks < 4; ks++) {
        const int rowQ = w * 16 + (mat & 1) * 8 + mi;
        const int ch   = 2 * ks + (mat >> 1);
        ldsm4(qf[ks], sQ + (rowQ * 8 + (ch ^ (rowQ & 7))) * 16);
    }

    float o[8][4];
    #pragma unroll
    for (int nf = 0; nf < 8; nf++)
        #pragma unroll
        for (int c = 0; c < 4; c++) o[nf][c] = 0.f;
    float m0 = -1e30f, m1 = -1e30f, l0 = 0.f, l1 = 0.f;

    const float SC2 = ATT_SCALE * LOG2E;

    for (int kt = 0; kt < ntk; kt++) {
        if (kt + 1 < ntk) { stageKV((kt + 1) & 1, kt + 1); cp_wait<1>(); }
        else              { cp_wait<0>(); }
        __syncthreads();

        const uint32_t sK = sKV + (kt & 1) * 1024 * 16;
        const uint32_t sV = sK + 512 * 16;

        float s[8][4];
        #pragma unroll
        for (int nf = 0; nf < 8; nf++)
            #pragma unroll
            for (int c = 0; c < 4; c++) s[nf][c] = 0.f;

        #pragma unroll
        for (int ks = 0; ks < 4; ks++) {
            unsigned bk[4][4];
            #pragma unroll
            for (int np = 0; np < 4; np++) {
                const int rowK = np * 16 + (mat & 1) * 8 + mi;
                const int ch   = 2 * ks + (mat >> 1);
                ldsm4(bk[np], sK + (rowK * 8 + (ch ^ (rowK & 7))) * 16);
            }
            #pragma unroll
            for (int nf = 0; nf < 8; nf++)
                mma16816(s[nf], qf[ks],
                         bk[nf >> 1][nf & 1], bk[nf >> 1][(nf & 1) + 2]);
        }

        float tmax0 = -1e30f, tmax1 = -1e30f;
        #pragma unroll
        for (int nf = 0; nf < 8; nf++) {
            const int col = kt * 64 + nf * 8 + 2 * q;
            const float2 mv = *(const float2*)&Ms[col];
            s[nf][0] = s[nf][0] * SC2 + mv.x;
            s[nf][1] = s[nf][1] * SC2 + mv.y;
            s[nf][2] = s[nf][2] * SC2 + mv.x;
            s[nf][3] = s[nf][3] * SC2 + mv.y;
            tmax0 = fmaxf(tmax0, fmaxf(s[nf][0], s[nf][1]));
            tmax1 = fmaxf(tmax1, fmaxf(s[nf][2], s[nf][3]));
        }
        #pragma unroll
        for (int off = 1; off <= 2; off <<= 1) {
            tmax0 = fmaxf(tmax0, __shfl_xor_sync(0xffffffffu, tmax0, off));
            tmax1 = fmaxf(tmax1, __shfl_xor_sync(0xffffffffu, tmax1, off));
        }
        const float nm0 = fmaxf(m0, tmax0);
        const float nm1 = fmaxf(m1, tmax1);
        const float cr0 = ex2(m0 - nm0);
        const float cr1 = ex2(m1 - nm1);
        l0 *= cr0; l1 *= cr1;
        #pragma unroll
        for (int nf = 0; nf < 8; nf++) {
            o[nf][0] *= cr0; o[nf][1] *= cr0;
            o[nf][2] *= cr1; o[nf][3] *= cr1;
        }
        m0 = nm0; m1 = nm1;

        #pragma unroll
        for (int nf = 0; nf < 8; nf++) {
            s[nf][0] = ex2(s[nf][0] - nm0);
            s[nf][1] = ex2(s[nf][1] - nm0);
            s[nf][2] = ex2(s[nf][2] - nm1);
            s[nf][3] = ex2(s[nf][3] - nm1);
            l0 += s[nf][0] + s[nf][1];
            l1 += s[nf][2] + s[nf][3];
        }

        unsigned ap[4][4];
        #pragma unroll
        for (int ks = 0; ks < 4; ks++) {
            ap[ks][0] = f2h2(s[2 * ks][0],     s[2 * ks][1]);
            ap[ks][1] = f2h2(s[2 * ks][2],     s[2 * ks][3]);
            ap[ks][2] = f2h2(s[2 * ks + 1][0], s[2 * ks + 1][1]);
            ap[ks][3] = f2h2(s[2 * ks + 1][2], s[2 * ks + 1][3]);
        }

        #pragma unroll
        for (int ks = 0; ks < 4; ks++) {
            unsigned bv[4][4];
            #pragma unroll
            for (int np = 0; np < 4; np++) {
                const int rowV = ks * 16 + (mat & 1) * 8 + mi;
                const int ch   = 2 * np + (mat >> 1);
                ldsm4t(bv[np], sV + (rowV * 8 + (ch ^ (rowV & 7))) * 16);
            }
            #pragma unroll
            for (int nf = 0; nf < 8; nf++)
                mma16816(o[nf], ap[ks],
                         bv[nf >> 1][(nf & 1) * 2], bv[nf >> 1][(nf & 1) * 2 + 1]);
        }
        __syncthreads();
    }

    #pragma unroll
    for (int off = 1; off <= 2; off <<= 1) {
        l0 += __shfl_xor_sync(0xffffffffu, l0, off);
        l1 += __shfl_xor_sync(0xffffffffu, l1, off);
    }
    const float inv0 = 1.f / l0;
    const float inv1 = 1.f / l1;

    const int row0 = b * NN + qt * 128 + w * 16 + r;
    #pragma unroll
    for (int nf = 0; nf < 8; nf++) {
        const int col = h * DD + nf * 8 + 2 * q;
        *(__half2*)&out[(size_t)row0 * CC + col] =
            __floats2half2_rn(o[nf][0] * inv0, o[nf][1] * inv0);
        *(__half2*)&out[(size_t)(row0 + 8) * CC + col] =
            __floats2half2_rn(o[nf][2] * inv1, o[nf][3] * inv1);
    }
}

// ---------------------------------------------------------------------------
// Launch
// ---------------------------------------------------------------------------
extern "C" void kernel_launch(void* const* d_in, const int* in_sizes, int n_in,
                              void* d_out, int out_size)
{
    const float* x      = (const float*)d_in[0];
    const float* amask  = (const float*)d_in[1];
    const float* W_qkv  = (const float*)d_in[2];
    const float* b_qkv  = (const float*)d_in[3];
    const float* W_proj = (const float*)d_in[4];
    const float* b_proj = (const float*)d_in[5];
    float* out = (float*)d_out;

    __half *x_h, *wqkv_t, *wproj_t, *qkv_h, *att_h;
    cudaGetSymbolAddress((void**)&x_h,     g_x_h);
    cudaGetSymbolAddress((void**)&wqkv_t,  g_wqkv_t);
    cudaGetSymbolAddress((void**)&wproj_t, g_wproj_t);
    cudaGetSymbolAddress((void**)&qkv_h,   g_qkv_h);
    cudaGetSymbolAddress((void**)&att_h,   g_att_h);

    static bool attr_set = false;
    if (!attr_set) {
        cudaFuncSetAttribute(gemm_f16_kernel<__half>,
                             cudaFuncAttributeMaxDynamicSharedMemorySize, GEMM_SMEM);
        cudaFuncSetAttribute(gemm_f16_kernel<float>,
                             cudaFuncAttributeMaxDynamicSharedMemorySize, GEMM_SMEM);
        cudaFuncSetAttribute(attn_f16_kernel,
                             cudaFuncAttributeMaxDynamicSharedMemorySize, AT_SMEM);
        attr_set = true;
    }

    // 0) conversions
    {
        const int n4 = M_ROWS * CC / 4;
        cvt_f32_f16_kernel<<<(n4 + 255) / 256, 256>>>(x, x_h, n4);
        transpose_cvt_kernel<<<dim3(QKV_COLS / 32, CC / 32), dim3(32, 8)>>>(
            W_qkv, wqkv_t, CC, QKV_COLS);
        transpose_cvt_kernel<<<dim3(CC / 32, CC / 32), dim3(32, 8)>>>(
            W_proj, wproj_t, CC, CC);
    }
    // 1) QKV projection (fp16 out), BK=64 GEMM
    {
        dim3 grid(QKV_COLS / 128, M_ROWS / 128);
        gemm_f16_kernel<__half><<<grid, 256, GEMM_SMEM>>>(
            x_h, wqkv_t, b_qkv, qkv_h, M_ROWS, CC, QKV_COLS);
    }
    // 2) Attention (fp16 out)
    {
        dim3 grid(BB * HH, NN / 128);
        attn_f16_kernel<<<grid, 256, AT_SMEM>>>(qkv_h, amask, att_h);
    }
    // 3) Output projection (fp32 out), BK=64 GEMM
    {
        dim3 grid(CC / 128, M_ROWS / 128);
        gemm_f16_kernel<float><<<grid, 256, GEMM_SMEM>>>(
            att_h, wproj_t, b_proj, out, M_ROWS, CC, CC);
    }
}

// round 9
// speedup vs baseline: 1.2271x; 1.0213x over previous
#include <cuda_runtime.h>
#include <cuda_fp16.h>
#include <cstdint>

#define BB 8
#define NN 1024
#define CC 768
#define HH 12
#define DD 64
#define M_ROWS (BB * NN)        // 8192
#define QKV_COLS (3 * CC)       // 2304
#define ATT_SCALE 0.125f
#define LOG2E 1.4426950408889634f

// Scratch (device globals: allocation-free)
__device__ __half g_x_h[(size_t)M_ROWS * CC];
__device__ __half g_wqkv_t[(size_t)QKV_COLS * CC];   // [2304][768] K-major
__device__ __half g_wproj_t[(size_t)CC * CC];        // [768][768]  K-major
__device__ __half g_qkv_h[(size_t)M_ROWS * QKV_COLS];
__device__ __half g_att_h[(size_t)M_ROWS * CC];

// ---------------------------------------------------------------------------
// PTX helpers
// ---------------------------------------------------------------------------
__device__ __forceinline__ unsigned sptr(const void* p) {
    return (unsigned)__cvta_generic_to_shared(p);
}
__device__ __forceinline__ void cp16(unsigned s, const void* g) {
    asm volatile("cp.async.cg.shared.global [%0], [%1], 16;\n" :: "r"(s), "l"(g));
}
__device__ __forceinline__ void cp_commit() {
    asm volatile("cp.async.commit_group;\n");
}
template <int N>
__device__ __forceinline__ void cp_wait() {
    asm volatile("cp.async.wait_group %0;\n" :: "n"(N));
}
__device__ __forceinline__ void ldsm4(unsigned r[4], unsigned a) {
    asm volatile("ldmatrix.sync.aligned.m8n8.x4.shared.b16 {%0,%1,%2,%3}, [%4];\n"
                 : "=r"(r[0]), "=r"(r[1]), "=r"(r[2]), "=r"(r[3]) : "r"(a));
}
__device__ __forceinline__ void ldsm4t(unsigned r[4], unsigned a) {
    asm volatile("ldmatrix.sync.aligned.m8n8.x4.trans.shared.b16 {%0,%1,%2,%3}, [%4];\n"
                 : "=r"(r[0]), "=r"(r[1]), "=r"(r[2]), "=r"(r[3]) : "r"(a));
}
__device__ __forceinline__ void mma16816(float c[4], const unsigned a[4],
                                         unsigned b0, unsigned b1) {
    asm volatile(
        "mma.sync.aligned.m16n8k16.row.col.f32.f16.f16.f32 "
        "{%0,%1,%2,%3},{%4,%5,%6,%7},{%8,%9},{%0,%1,%2,%3};\n"
        : "+f"(c[0]), "+f"(c[1]), "+f"(c[2]), "+f"(c[3])
        : "r"(a[0]), "r"(a[1]), "r"(a[2]), "r"(a[3]), "r"(b0), "r"(b1));
}
__device__ __forceinline__ unsigned f2h2(float lo, float hi) {
    __half2 h = __floats2half2_rn(lo, hi);
    return *(unsigned*)&h;
}
__device__ __forceinline__ float ex2(float x) {
    float r;
    asm("ex2.approx.f32 %0, %1;" : "=f"(r) : "f"(x));
    return r;
}
__device__ __forceinline__ void store2(__half* p, float x, float y) {
    *(__half2*)p = __floats2half2_rn(x, y);
}
__device__ __forceinline__ void store2(float* p, float x, float y) {
    *(float2*)p = make_float2(x, y);
}

// ---------------------------------------------------------------------------
// conversions
// ---------------------------------------------------------------------------
__global__ void cvt_f32_f16_kernel(const float* __restrict__ in,
                                   __half* __restrict__ out, int n4) {
    int i = blockIdx.x * 256 + threadIdx.x;
    if (i < n4) {
        float4 v = ((const float4*)in)[i];
        __half2 h0 = __floats2half2_rn(v.x, v.y);
        __half2 h1 = __floats2half2_rn(v.z, v.w);
        ((uint2*)out)[i] = make_uint2(*(unsigned*)&h0, *(unsigned*)&h1);
    }
}

__global__ void transpose_cvt_kernel(const float* __restrict__ W,
                                     __half* __restrict__ Wt,
                                     int rows, int cols) {
    __shared__ float t[32][33];
    const int x  = blockIdx.x * 32 + threadIdx.x;
    const int y0 = blockIdx.y * 32 + threadIdx.y;
    #pragma unroll
    for (int i = 0; i < 4; i++)
        t[threadIdx.y + i * 8][threadIdx.x] = W[(size_t)(y0 + i * 8) * cols + x];
    __syncthreads();
    const int xo  = blockIdx.y * 32 + threadIdx.x;
    const int yo0 = blockIdx.x * 32 + threadIdx.y;
    #pragma unroll
    for (int i = 0; i < 4; i++)
        Wt[(size_t)(yo0 + i * 8) * rows + xo] =
            __float2half(t[threadIdx.x][threadIdx.y + i * 8]);
}

// ---------------------------------------------------------------------------
// fp16 tensor-core GEMM (R7 config — frozen): 128x128 tile, BK=64, 2-stage.
// ---------------------------------------------------------------------------
#define G_ASZ   16384
#define G_STAGE (2 * G_ASZ)
#define GEMM_SMEM (2 * G_STAGE)

template <typename OutT>
__global__ __launch_bounds__(256) void gemm_f16_kernel(
    const __half* __restrict__ A, const __half* __restrict__ Bt,
    const float* __restrict__ bias, OutT* __restrict__ C,
    int M, int Kdim, int Ncols)
{
    extern __shared__ char smem[];
    const uint32_t sb = sptr(smem);

    const int tid  = threadIdx.x;
    const int lane = tid & 31;
    const int wid  = tid >> 5;
    const int wm   = wid >> 1;
    const int wn   = wid & 1;
    const int r    = lane >> 2;
    const int q    = lane & 3;
    const int mat  = lane >> 3;
    const int mi   = lane & 7;

    const int rowBase = blockIdx.y * 128;
    const int colBase = blockIdx.x * 128;

    float acc[2][8][4];
    #pragma unroll
    for (int mb = 0; mb < 2; mb++)
        #pragma unroll
        for (int nf = 0; nf < 8; nf++)
            #pragma unroll
            for (int c = 0; c < 4; c++) acc[mb][nf][c] = 0.f;

    const int nt = Kdim >> 6;

    auto stage = [&](int buf, int k0) {
        const uint32_t base = sb + buf * G_STAGE;
        #pragma unroll
        for (int i = 0; i < 4; i++) {
            const int j   = i * 256 + tid;
            const int row = j >> 3;
            const int c   = j & 7;
            const uint32_t soff = row * 128 + ((c ^ (row & 7)) * 16);
            cp16(base + soff,
                 A + (size_t)(rowBase + row) * Kdim + k0 + c * 8);
            cp16(base + G_ASZ + soff,
                 Bt + (size_t)(colBase + row) * Kdim + k0 + c * 8);
        }
        cp_commit();
    };

    stage(0, 0);

    for (int it = 0; it < nt; it++) {
        if (it + 1 < nt) { stage((it + 1) & 1, (it + 1) * 64); cp_wait<1>(); }
        else             { cp_wait<0>(); }
        __syncthreads();

        const uint32_t bA = sb + (it & 1) * G_STAGE;
        const uint32_t bB = bA + G_ASZ;

        #pragma unroll
        for (int ks = 0; ks < 4; ks++) {
            const int chb = 2 * ks + (mat >> 1);
            unsigned af[2][4];
            #pragma unroll
            for (int mb = 0; mb < 2; mb++) {
                const int rowA = wm * 32 + mb * 16 + (mat & 1) * 8 + mi;
                ldsm4(af[mb], bA + rowA * 128 + ((chb ^ (rowA & 7)) * 16));
            }
            unsigned bf[4][4];
            #pragma unroll
            for (int np = 0; np < 4; np++) {
                const int rowB = wn * 64 + np * 16 + (mat & 1) * 8 + mi;
                ldsm4(bf[np], bB + rowB * 128 + ((chb ^ (rowB & 7)) * 16));
            }
            #pragma unroll
            for (int mb = 0; mb < 2; mb++)
                #pragma unroll
                for (int nf = 0; nf < 8; nf++)
                    mma16816(acc[mb][nf], af[mb],
                             bf[nf >> 1][nf & 1], bf[nf >> 1][(nf & 1) + 2]);
        }
        __syncthreads();
    }

    #pragma unroll
    for (int mb = 0; mb < 2; mb++) {
        const int row0 = rowBase + wm * 32 + mb * 16 + r;
        #pragma unroll
        for (int nf = 0; nf < 8; nf++) {
            const int col = colBase + wn * 64 + nf * 8 + 2 * q;
            const float2 bv = *(const float2*)&bias[col];
            store2(&C[(size_t)row0 * Ncols + col],
                   acc[mb][nf][0] + bv.x, acc[mb][nf][1] + bv.y);
            store2(&C[(size_t)(row0 + 8) * Ncols + col],
                   acc[mb][nf][2] + bv.x, acc[mb][nf][3] + bv.y);
        }
    }
}

// ---------------------------------------------------------------------------
// fp16 flash attention. CTA = (b,h, 128 q-rows), 8 warps, 256 thr.
// R8: pair-wise key tiles (4 staging buffers of 64 keys; barriers halved) +
// max-unchanged rescale skip (bit-identical). Tile-skip + exp2 domain kept.
// smem: Q[0,16K), KV 4x16K [16K,80K), Mask[80K,84K), sP. Total ~84KB.
// ---------------------------------------------------------------------------
#define AT_Q    0
#define AT_KV   16384
#define AT_M    81920
#define AT_P    86016
#define AT_SMEM (AT_P + 16)

__global__ __launch_bounds__(256, 2) void attn_f16_kernel(
    const __half* __restrict__ qkv, const float* __restrict__ mask,
    __half* __restrict__ out)
{
    extern __shared__ char smem[];
    const uint32_t sb  = sptr(smem);
    const uint32_t sQ  = sb + AT_Q;
    const uint32_t sKV = sb + AT_KV;
    float* Ms = (float*)(smem + AT_M);
    int* sP   = (int*)(smem + AT_P);

    const int bh = blockIdx.x;
    const int b  = bh / HH;
    const int h  = bh % HH;
    const int qt = blockIdx.y;

    const int tid  = threadIdx.x;
    const int lane = tid & 31;
    const int w    = tid >> 5;
    const int r    = lane >> 2;
    const int q    = lane & 3;
    const int mat  = lane >> 3;
    const int mi   = lane & 7;

    if (tid == 0) *sP = NN;

    // stage Q: 128 rows x 8 chunks
    #pragma unroll
    for (int i = 0; i < 4; i++) {
        const int j = tid + i * 256;
        const int row = j >> 3, c0 = j & 7;
        cp16(sQ + (row * 8 + (c0 ^ (row & 7))) * 16,
             qkv + (size_t)(b * NN + qt * 128 + row) * QKV_COLS + h * DD + c0 * 8);
    }
    cp_commit();

    // stage a PAIR of 64-key tiles (kt0, kt0+1) into buffers bp*2, bp*2+1
    auto stage_pair = [&](int bp, int kt0) {
        #pragma unroll
        for (int t = 0; t < 2; t++) {
            const int buf = bp * 2 + t;
            const int kt  = kt0 + t;
            #pragma unroll
            for (int i = 0; i < 4; i++) {
                const int j  = tid + i * 256;
                const int kv = j >> 9;
                const int jj = j & 511;
                const int row = jj >> 3, c0 = jj & 7;
                cp16(sKV + buf * 16384 + kv * 8192 +
                         (row * 8 + (c0 ^ (row & 7))) * 16,
                     qkv + (size_t)(b * NN + kt * 64 + row) * QKV_COLS +
                         (kv + 1) * CC + h * DD + c0 * 8);
            }
        }
        cp_commit();
    };

    stage_pair(0, 0);

    // stage mask (pre-multiplied by log2e)
    {
        float4 mv = ((const float4*)(mask + b * NN))[tid];
        mv.x *= LOG2E; mv.y *= LOG2E; mv.z *= LOG2E; mv.w *= LOG2E;
        ((float4*)Ms)[tid] = mv;
    }

    cp_wait<0>();
    __syncthreads();

    // first padded position -> number of valid key tiles
    {
        int firstPad = NN;
        #pragma unroll
        for (int i = 0; i < 4; i++) {
            const int idx = tid * 4 + i;
            if (Ms[idx] < -1e8f) { firstPad = idx; break; }
        }
        if (firstPad < NN) atomicMin(sP, firstPad);
    }
    __syncthreads();
    const int ntk    = (*sP + 63) >> 6;
    const int npairs = (ntk + 1) >> 1;

    // Q fragments, persistent
    unsigned qf[4][4];
    #pragma unroll
    for (int ks = 0; ks < 4; ks++) {
        const int rowQ = w * 16 + (mat & 1) * 8 + mi;
        const int ch   = 2 * ks + (mat >> 1);
        ldsm4(qf[ks], sQ + (rowQ * 8 + (ch ^ (rowQ & 7))) * 16);
    }

    float o[8][4];
    #pragma unroll
    for (int nf = 0; nf < 8; nf++)
        #pragma unroll
        for (int c = 0; c < 4; c++) o[nf][c] = 0.f;
    float m0 = -1e30f, m1 = -1e30f, l0 = 0.f, l1 = 0.f;

    const float SC2 = ATT_SCALE * LOG2E;

    for (int p = 0; p < npairs; p++) {
        if (p + 1 < npairs) { stage_pair((p + 1) & 1, (p + 1) * 2); cp_wait<1>(); }
        else                { cp_wait<0>(); }
        __syncthreads();

        const uint32_t pairBase = sKV + ((p & 1) * 2) * 16384;

        #pragma unroll
        for (int t = 0; t < 2; t++) {
            const int kt = p * 2 + t;
            if (kt >= ntk) break;
            const uint32_t sK = pairBase + t * 16384;
            const uint32_t sV = sK + 8192;

            // ---- S = Q K^T ----
            float s[8][4];
            #pragma unroll
            for (int nf = 0; nf < 8; nf++)
                #pragma unroll
                for (int c = 0; c < 4; c++) s[nf][c] = 0.f;

            #pragma unroll
            for (int ks = 0; ks < 4; ks++) {
                unsigned bk[4][4];
                #pragma unroll
                for (int np = 0; np < 4; np++) {
                    const int rowK = np * 16 + (mat & 1) * 8 + mi;
                    const int ch   = 2 * ks + (mat >> 1);
                    ldsm4(bk[np], sK + (rowK * 8 + (ch ^ (rowK & 7))) * 16);
                }
                #pragma unroll
                for (int nf = 0; nf < 8; nf++)
                    mma16816(s[nf], qf[ks],
                             bk[nf >> 1][nf & 1], bk[nf >> 1][(nf & 1) + 2]);
            }

            // ---- scale + mask (exp2 domain) + online softmax ----
            float tmax0 = -1e30f, tmax1 = -1e30f;
            #pragma unroll
            for (int nf = 0; nf < 8; nf++) {
                const int col = kt * 64 + nf * 8 + 2 * q;
                const float2 mv = *(const float2*)&Ms[col];
                s[nf][0] = s[nf][0] * SC2 + mv.x;
                s[nf][1] = s[nf][1] * SC2 + mv.y;
                s[nf][2] = s[nf][2] * SC2 + mv.x;
                s[nf][3] = s[nf][3] * SC2 + mv.y;
                tmax0 = fmaxf(tmax0, fmaxf(s[nf][0], s[nf][1]));
                tmax1 = fmaxf(tmax1, fmaxf(s[nf][2], s[nf][3]));
            }
            #pragma unroll
            for (int off = 1; off <= 2; off <<= 1) {
                tmax0 = fmaxf(tmax0, __shfl_xor_sync(0xffffffffu, tmax0, off));
                tmax1 = fmaxf(tmax1, __shfl_xor_sync(0xffffffffu, tmax1, off));
            }
            const float nm0 = fmaxf(m0, tmax0);
            const float nm1 = fmaxf(m1, tmax1);
            // rescale only if some row's max changed (warp-uniform branch;
            // skipping when unchanged is bit-identical since cr would be 1.0)
            if (__any_sync(0xffffffffu, (nm0 > m0) | (nm1 > m1))) {
                const float cr0 = ex2(m0 - nm0);
                const float cr1 = ex2(m1 - nm1);
                l0 *= cr0; l1 *= cr1;
                #pragma unroll
                for (int nf = 0; nf < 8; nf++) {
                    o[nf][0] *= cr0; o[nf][1] *= cr0;
                    o[nf][2] *= cr1; o[nf][3] *= cr1;
                }
                m0 = nm0; m1 = nm1;
            }

            #pragma unroll
            for (int nf = 0; nf < 8; nf++) {
                s[nf][0] = ex2(s[nf][0] - m0);
                s[nf][1] = ex2(s[nf][1] - m0);
                s[nf][2] = ex2(s[nf][2] - m1);
                s[nf][3] = ex2(s[nf][3] - m1);
                l0 += s[nf][0] + s[nf][1];
                l1 += s[nf][2] + s[nf][3];
            }

            // ---- P fragments in registers ----
            unsigned ap[4][4];
            #pragma unroll
            for (int ks = 0; ks < 4; ks++) {
                ap[ks][0] = f2h2(s[2 * ks][0],     s[2 * ks][1]);
                ap[ks][1] = f2h2(s[2 * ks][2],     s[2 * ks][3]);
                ap[ks][2] = f2h2(s[2 * ks + 1][0], s[2 * ks + 1][1]);
                ap[ks][3] = f2h2(s[2 * ks + 1][2], s[2 * ks + 1][3]);
            }

            // ---- O += P V ----
            #pragma unroll
            for (int ks = 0; ks < 4; ks++) {
                unsigned bv[4][4];
                #pragma unroll
                for (int np = 0; np < 4; np++) {
                    const int rowV = ks * 16 + (mat & 1) * 8 + mi;
                    const int ch   = 2 * np + (mat >> 1);
                    ldsm4t(bv[np], sV + (rowV * 8 + (ch ^ (rowV & 7))) * 16);
                }
                #pragma unroll
                for (int nf = 0; nf < 8; nf++)
                    mma16816(o[nf], ap[ks],
                             bv[nf >> 1][(nf & 1) * 2], bv[nf >> 1][(nf & 1) * 2 + 1]);
            }
        }
        __syncthreads();
    }

    // ---- finalize ----
    #pragma unroll
    for (int off = 1; off <= 2; off <<= 1) {
        l0 += __shfl_xor_sync(0xffffffffu, l0, off);
        l1 += __shfl_xor_sync(0xffffffffu, l1, off);
    }
    const float inv0 = 1.f / l0;
    const float inv1 = 1.f / l1;

    const int row0 = b * NN + qt * 128 + w * 16 + r;
    #pragma unroll
    for (int nf = 0; nf < 8; nf++) {
        const int col = h * DD + nf * 8 + 2 * q;
        *(__half2*)&out[(size_t)row0 * CC + col] =
            __floats2half2_rn(o[nf][0] * inv0, o[nf][1] * inv0);
        *(__half2*)&out[(size_t)(row0 + 8) * CC + col] =
            __floats2half2_rn(o[nf][2] * inv1, o[nf][3] * inv1);
    }
}

// ---------------------------------------------------------------------------
// Launch
// ---------------------------------------------------------------------------
extern "C" void kernel_launch(void* const* d_in, const int* in_sizes, int n_in,
                              void* d_out, int out_size)
{
    const float* x      = (const float*)d_in[0];
    const float* amask  = (const float*)d_in[1];
    const float* W_qkv  = (const float*)d_in[2];
    const float* b_qkv  = (const float*)d_in[3];
    const float* W_proj = (const float*)d_in[4];
    const float* b_proj = (const float*)d_in[5];
    float* out = (float*)d_out;

    __half *x_h, *wqkv_t, *wproj_t, *qkv_h, *att_h;
    cudaGetSymbolAddress((void**)&x_h,     g_x_h);
    cudaGetSymbolAddress((void**)&wqkv_t,  g_wqkv_t);
    cudaGetSymbolAddress((void**)&wproj_t, g_wproj_t);
    cudaGetSymbolAddress((void**)&qkv_h,   g_qkv_h);
    cudaGetSymbolAddress((void**)&att_h,   g_att_h);

    static bool attr_set = false;
    if (!attr_set) {
        cudaFuncSetAttribute(gemm_f16_kernel<__half>,
                             cudaFuncAttributeMaxDynamicSharedMemorySize, GEMM_SMEM);
        cudaFuncSetAttribute(gemm_f16_kernel<float>,
                             cudaFuncAttributeMaxDynamicSharedMemorySize, GEMM_SMEM);
        cudaFuncSetAttribute(attn_f16_kernel,
                             cudaFuncAttributeMaxDynamicSharedMemorySize, AT_SMEM);
        attr_set = true;
    }

    // 0) conversions
    {
        const int n4 = M_ROWS * CC / 4;
        cvt_f32_f16_kernel<<<(n4 + 255) / 256, 256>>>(x, x_h, n4);
        transpose_cvt_kernel<<<dim3(QKV_COLS / 32, CC / 32), dim3(32, 8)>>>(
            W_qkv, wqkv_t, CC, QKV_COLS);
        transpose_cvt_kernel<<<dim3(CC / 32, CC / 32), dim3(32, 8)>>>(
            W_proj, wproj_t, CC, CC);
    }
    // 1) QKV projection (fp16 out)
    {
        dim3 grid(QKV_COLS / 128, M_ROWS / 128);
        gemm_f16_kernel<__half><<<grid, 256, GEMM_SMEM>>>(
            x_h, wqkv_t, b_qkv, qkv_h, M_ROWS, CC, QKV_COLS);
    }
    // 2) Attention (fp16 out)
    {
        dim3 grid(BB * HH, NN / 128);
        attn_f16_kernel<<<grid, 256, AT_SMEM>>>(qkv_h, amask, att_h);
    }
    // 3) Output projection (fp32 out)
    {
        dim3 grid(CC / 128, M_ROWS / 128);
        gemm_f16_kernel<float><<<grid, 256, GEMM_SMEM>>>(
            att_h, wproj_t, b_proj, out, M_ROWS, CC, CC);
    }
}

// round 10
// speedup vs baseline: 1.2349x; 1.0063x over previous
#include <cuda_runtime.h>
#include <cuda_fp16.h>
#include <cstdint>

#define BB 8
#define NN 1024
#define CC 768
#define HH 12
#define DD 64
#define M_ROWS (BB * NN)        // 8192
#define QKV_COLS (3 * CC)       // 2304
#define ATT_SCALE 0.125f
#define LOG2E 1.4426950408889634f

// Scratch (device globals: allocation-free)
__device__ __half g_x_h[(size_t)M_ROWS * CC];
__device__ __half g_wqkv_t[(size_t)QKV_COLS * CC];   // [2304][768] K-major
__device__ __half g_wproj_t[(size_t)CC * CC];        // [768][768]  K-major
__device__ __half g_qkv_h[(size_t)M_ROWS * QKV_COLS];
__device__ __half g_att_h[(size_t)M_ROWS * CC];

// ---------------------------------------------------------------------------
// PTX helpers
// ---------------------------------------------------------------------------
__device__ __forceinline__ unsigned sptr(const void* p) {
    return (unsigned)__cvta_generic_to_shared(p);
}
__device__ __forceinline__ void cp16(unsigned s, const void* g) {
    asm volatile("cp.async.cg.shared.global [%0], [%1], 16;\n" :: "r"(s), "l"(g));
}
__device__ __forceinline__ void cp_commit() {
    asm volatile("cp.async.commit_group;\n");
}
template <int N>
__device__ __forceinline__ void cp_wait() {
    asm volatile("cp.async.wait_group %0;\n" :: "n"(N));
}
__device__ __forceinline__ void ldsm4(unsigned r[4], unsigned a) {
    asm volatile("ldmatrix.sync.aligned.m8n8.x4.shared.b16 {%0,%1,%2,%3}, [%4];\n"
                 : "=r"(r[0]), "=r"(r[1]), "=r"(r[2]), "=r"(r[3]) : "r"(a));
}
__device__ __forceinline__ void ldsm4t(unsigned r[4], unsigned a) {
    asm volatile("ldmatrix.sync.aligned.m8n8.x4.trans.shared.b16 {%0,%1,%2,%3}, [%4];\n"
                 : "=r"(r[0]), "=r"(r[1]), "=r"(r[2]), "=r"(r[3]) : "r"(a));
}
__device__ __forceinline__ void mma16816(float c[4], const unsigned a[4],
                                         unsigned b0, unsigned b1) {
    asm volatile(
        "mma.sync.aligned.m16n8k16.row.col.f32.f16.f16.f32 "
        "{%0,%1,%2,%3},{%4,%5,%6,%7},{%8,%9},{%0,%1,%2,%3};\n"
        : "+f"(c[0]), "+f"(c[1]), "+f"(c[2]), "+f"(c[3])
        : "r"(a[0]), "r"(a[1]), "r"(a[2]), "r"(a[3]), "r"(b0), "r"(b1));
}
__device__ __forceinline__ unsigned f2h2(float lo, float hi) {
    __half2 h = __floats2half2_rn(lo, hi);
    return *(unsigned*)&h;
}
__device__ __forceinline__ float ex2(float x) {
    float r;
    asm("ex2.approx.f32 %0, %1;" : "=f"(r) : "f"(x));
    return r;
}
__device__ __forceinline__ void store2(__half* p, float x, float y) {
    *(__half2*)p = __floats2half2_rn(x, y);
}
__device__ __forceinline__ void store2(float* p, float x, float y) {
    *(float2*)p = make_float2(x, y);
}

// ---------------------------------------------------------------------------
// fused prep: x f32->f16 + both weight transposes, one launch.
// blocks [0,CVT_B): cvt; [CVT_B, CVT_B+TQ_B): W_qkv; rest: W_proj.
// ---------------------------------------------------------------------------
#define CVT_B 6144                        // M_ROWS*CC/4/256
#define TQ_BX (QKV_COLS / 32)             // 72
#define TQ_B  (TQ_BX * (CC / 32))         // 1728
#define TP_BX (CC / 32)                   // 24
#define TP_B  (TP_BX * (CC / 32))         // 576
#define PREP_BLOCKS (CVT_B + TQ_B + TP_B) // 8448

__global__ __launch_bounds__(256) void prep_kernel(
    const float* __restrict__ x, __half* __restrict__ x_h,
    const float* __restrict__ Wq, __half* __restrict__ Wq_t,
    const float* __restrict__ Wp, __half* __restrict__ Wp_t)
{
    __shared__ float t[32][33];
    const int bid = blockIdx.x;
    const int tid = threadIdx.x;

    if (bid < CVT_B) {
        const int i = bid * 256 + tid;
        float4 v = ((const float4*)x)[i];
        __half2 h0 = __floats2half2_rn(v.x, v.y);
        __half2 h1 = __floats2half2_rn(v.z, v.w);
        ((uint2*)x_h)[i] = make_uint2(*(unsigned*)&h0, *(unsigned*)&h1);
        return;
    }

    const float* W; __half* Wt; int cols, bx, by;
    if (bid < CVT_B + TQ_B) {
        const int b2 = bid - CVT_B;
        W = Wq; Wt = Wq_t; cols = QKV_COLS;
        bx = b2 % TQ_BX; by = b2 / TQ_BX;
    } else {
        const int b2 = bid - CVT_B - TQ_B;
        W = Wp; Wt = Wp_t; cols = CC;
        bx = b2 % TP_BX; by = b2 / TP_BX;
    }
    const int tx = tid & 31, ty = tid >> 5;
    #pragma unroll
    for (int i = 0; i < 4; i++)
        t[ty + i * 8][tx] = W[(size_t)(by * 32 + ty + i * 8) * cols + bx * 32 + tx];
    __syncthreads();
    #pragma unroll
    for (int i = 0; i < 4; i++)
        Wt[(size_t)(bx * 32 + ty + i * 8) * CC + by * 32 + tx] =
            __float2half(t[tx][ty + i * 8]);
}

// ---------------------------------------------------------------------------
// fp16 tensor-core GEMM: 128x128 tile, BK=64, 3-stage cp.async pipeline with
// SINGLE barrier per iteration (stage(it+2) after BAR reuses the buffer
// compute(it-1) just released; cp_wait<1> guarantees buffer it resident).
// 256 threads, 8 warps (4m x 2n), warp tile 32x64. 2 CTAs/SM.
// smem rows: 128B (64 halves) = 8 chunks of 16B; swizzle c ^= row&7.
// ---------------------------------------------------------------------------
#define G_ASZ   16384
#define G_STAGE (2 * G_ASZ)           // 32 KB per stage
#define GEMM_SMEM (3 * G_STAGE)       // 96 KB

template <typename OutT>
__global__ __launch_bounds__(256, 2) void gemm_f16_kernel(
    const __half* __restrict__ A, const __half* __restrict__ Bt,
    const float* __restrict__ bias, OutT* __restrict__ C,
    int M, int Kdim, int Ncols)
{
    extern __shared__ char smem[];
    const uint32_t sb = sptr(smem);

    const int tid  = threadIdx.x;
    const int lane = tid & 31;
    const int wid  = tid >> 5;
    const int wm   = wid >> 1;
    const int wn   = wid & 1;
    const int r    = lane >> 2;
    const int q    = lane & 3;
    const int mat  = lane >> 3;
    const int mi   = lane & 7;

    const int rowBase = blockIdx.y * 128;
    const int colBase = blockIdx.x * 128;

    float acc[2][8][4];
    #pragma unroll
    for (int mb = 0; mb < 2; mb++)
        #pragma unroll
        for (int nf = 0; nf < 8; nf++)
            #pragma unroll
            for (int c = 0; c < 4; c++) acc[mb][nf][c] = 0.f;

    const int nt = Kdim >> 6;          // BK=64

    auto stage = [&](int buf, int k0) {
        const uint32_t base = sb + buf * G_STAGE;
        #pragma unroll
        for (int i = 0; i < 4; i++) {
            const int j   = i * 256 + tid;
            const int row = j >> 3;
            const int c   = j & 7;
            const uint32_t soff = row * 128 + ((c ^ (row & 7)) * 16);
            cp16(base + soff,
                 A + (size_t)(rowBase + row) * Kdim + k0 + c * 8);
            cp16(base + G_ASZ + soff,
                 Bt + (size_t)(colBase + row) * Kdim + k0 + c * 8);
        }
        cp_commit();
    };

    stage(0, 0);
    stage(1, 64);

    int cur = 0;                       // it % 3
    for (int it = 0; it < nt; it++) {
        if (it + 1 < nt) cp_wait<1>(); else cp_wait<0>();
        __syncthreads();
        if (it + 2 < nt) {
            int nb = cur + 2; if (nb >= 3) nb -= 3;
            stage(nb, (it + 2) * 64);
        }

        const uint32_t bA = sb + cur * G_STAGE;
        const uint32_t bB = bA + G_ASZ;

        #pragma unroll
        for (int ks = 0; ks < 4; ks++) {
            const int chb = 2 * ks + (mat >> 1);
            unsigned af[2][4];
            #pragma unroll
            for (int mb = 0; mb < 2; mb++) {
                const int rowA = wm * 32 + mb * 16 + (mat & 1) * 8 + mi;
                ldsm4(af[mb], bA + rowA * 128 + ((chb ^ (rowA & 7)) * 16));
            }
            unsigned bf[4][4];
            #pragma unroll
            for (int np = 0; np < 4; np++) {
                const int rowB = wn * 64 + np * 16 + (mat & 1) * 8 + mi;
                ldsm4(bf[np], bB + rowB * 128 + ((chb ^ (rowB & 7)) * 16));
            }
            #pragma unroll
            for (int mb = 0; mb < 2; mb++)
                #pragma unroll
                for (int nf = 0; nf < 8; nf++)
                    mma16816(acc[mb][nf], af[mb],
                             bf[nf >> 1][nf & 1], bf[nf >> 1][(nf & 1) + 2]);
        }
        if (++cur == 3) cur = 0;
    }

    #pragma unroll
    for (int mb = 0; mb < 2; mb++) {
        const int row0 = rowBase + wm * 32 + mb * 16 + r;
        #pragma unroll
        for (int nf = 0; nf < 8; nf++) {
            const int col = colBase + wn * 64 + nf * 8 + 2 * q;
            const float2 bv = *(const float2*)&bias[col];
            store2(&C[(size_t)row0 * Ncols + col],
                   acc[mb][nf][0] + bv.x, acc[mb][nf][1] + bv.y);
            store2(&C[(size_t)(row0 + 8) * Ncols + col],
                   acc[mb][nf][2] + bv.x, acc[mb][nf][3] + bv.y);
        }
    }
}

// ---------------------------------------------------------------------------
// fp16 flash attention (R8 config — unchanged).
// ---------------------------------------------------------------------------
#define AT_Q    0
#define AT_KV   16384
#define AT_M    81920
#define AT_P    86016
#define AT_SMEM (AT_P + 16)

__global__ __launch_bounds__(256, 2) void attn_f16_kernel(
    const __half* __restrict__ qkv, const float* __restrict__ mask,
    __half* __restrict__ out)
{
    extern __shared__ char smem[];
    const uint32_t sb  = sptr(smem);
    const uint32_t sQ  = sb + AT_Q;
    const uint32_t sKV = sb + AT_KV;
    float* Ms = (float*)(smem + AT_M);
    int* sP   = (int*)(smem + AT_P);

    const int bh = blockIdx.x;
    const int b  = bh / HH;
    const int h  = bh % HH;
    const int qt = blockIdx.y;

    const int tid  = threadIdx.x;
    const int lane = tid & 31;
    const int w    = tid >> 5;
    const int r    = lane >> 2;
    const int q    = lane & 3;
    const int mat  = lane >> 3;
    const int mi   = lane & 7;

    if (tid == 0) *sP = NN;

    #pragma unroll
    for (int i = 0; i < 4; i++) {
        const int j = tid + i * 256;
        const int row = j >> 3, c0 = j & 7;
        cp16(sQ + (row * 8 + (c0 ^ (row & 7))) * 16,
             qkv + (size_t)(b * NN + qt * 128 + row) * QKV_COLS + h * DD + c0 * 8);
    }
    cp_commit();

    auto stage_pair = [&](int bp, int kt0) {
        #pragma unroll
        for (int t = 0; t < 2; t++) {
            const int buf = bp * 2 + t;
            const int kt  = kt0 + t;
            #pragma unroll
            for (int i = 0; i < 4; i++) {
                const int j  = tid + i * 256;
                const int kv = j >> 9;
                const int jj = j & 511;
                const int row = jj >> 3, c0 = jj & 7;
                cp16(sKV + buf * 16384 + kv * 8192 +
                         (row * 8 + (c0 ^ (row & 7))) * 16,
                     qkv + (size_t)(b * NN + kt * 64 + row) * QKV_COLS +
                         (kv + 1) * CC + h * DD + c0 * 8);
            }
        }
        cp_commit();
    };

    stage_pair(0, 0);

    {
        float4 mv = ((const float4*)(mask + b * NN))[tid];
        mv.x *= LOG2E; mv.y *= LOG2E; mv.z *= LOG2E; mv.w *= LOG2E;
        ((float4*)Ms)[tid] = mv;
    }

    cp_wait<0>();
    __syncthreads();

    {
        int firstPad = NN;
        #pragma unroll
        for (int i = 0; i < 4; i++) {
            const int idx = tid * 4 + i;
            if (Ms[idx] < -1e8f) { firstPad = idx; break; }
        }
        if (firstPad < NN) atomicMin(sP, firstPad);
    }
    __syncthreads();
    const int ntk    = (*sP + 63) >> 6;
    const int npairs = (ntk + 1) >> 1;

    unsigned qf[4][4];
    #pragma unroll
    for (int ks = 0; ks < 4; ks++) {
        const int rowQ = w * 16 + (mat & 1) * 8 + mi;
        const int ch   = 2 * ks + (mat >> 1);
        ldsm4(qf[ks], sQ + (rowQ * 8 + (ch ^ (rowQ & 7))) * 16);
    }

    float o[8][4];
    #pragma unroll
    for (int nf = 0; nf < 8; nf++)
        #pragma unroll
        for (int c = 0; c < 4; c++) o[nf][c] = 0.f;
    float m0 = -1e30f, m1 = -1e30f, l0 = 0.f, l1 = 0.f;

    const float SC2 = ATT_SCALE * LOG2E;

    for (int p = 0; p < npairs; p++) {
        if (p + 1 < npairs) { stage_pair((p + 1) & 1, (p + 1) * 2); cp_wait<1>(); }
        else                { cp_wait<0>(); }
        __syncthreads();

        const uint32_t pairBase = sKV + ((p & 1) * 2) * 16384;

        #pragma unroll
        for (int t = 0; t < 2; t++) {
            const int kt = p * 2 + t;
            if (kt >= ntk) break;
            const uint32_t sK = pairBase + t * 16384;
            const uint32_t sV = sK + 8192;

            float s[8][4];
            #pragma unroll
            for (int nf = 0; nf < 8; nf++)
                #pragma unroll
                for (int c = 0; c < 4; c++) s[nf][c] = 0.f;

            #pragma unroll
            for (int ks = 0; ks < 4; ks++) {
                unsigned bk[4][4];
                #pragma unroll
                for (int np = 0; np < 4; np++) {
                    const int rowK = np * 16 + (mat & 1) * 8 + mi;
                    const int ch   = 2 * ks + (mat >> 1);
                    ldsm4(bk[np], sK + (rowK * 8 + (ch ^ (rowK & 7))) * 16);
                }
                #pragma unroll
                for (int nf = 0; nf < 8; nf++)
                    mma16816(s[nf], qf[ks],
                             bk[nf >> 1][nf & 1], bk[nf >> 1][(nf & 1) + 2]);
            }

            float tmax0 = -1e30f, tmax1 = -1e30f;
            #pragma unroll
            for (int nf = 0; nf < 8; nf++) {
                const int col = kt * 64 + nf * 8 + 2 * q;
                const float2 mv = *(const float2*)&Ms[col];
                s[nf][0] = s[nf][0] * SC2 + mv.x;
                s[nf][1] = s[nf][1] * SC2 + mv.y;
                s[nf][2] = s[nf][2] * SC2 + mv.x;
                s[nf][3] = s[nf][3] * SC2 + mv.y;
                tmax0 = fmaxf(tmax0, fmaxf(s[nf][0], s[nf][1]));
                tmax1 = fmaxf(tmax1, fmaxf(s[nf][2], s[nf][3]));
            }
            #pragma unroll
            for (int off = 1; off <= 2; off <<= 1) {
                tmax0 = fmaxf(tmax0, __shfl_xor_sync(0xffffffffu, tmax0, off));
                tmax1 = fmaxf(tmax1, __shfl_xor_sync(0xffffffffu, tmax1, off));
            }
            const float nm0 = fmaxf(m0, tmax0);
            const float nm1 = fmaxf(m1, tmax1);
            if (__any_sync(0xffffffffu, (nm0 > m0) | (nm1 > m1))) {
                const float cr0 = ex2(m0 - nm0);
                const float cr1 = ex2(m1 - nm1);
                l0 *= cr0; l1 *= cr1;
                #pragma unroll
                for (int nf = 0; nf < 8; nf++) {
                    o[nf][0] *= cr0; o[nf][1] *= cr0;
                    o[nf][2] *= cr1; o[nf][3] *= cr1;
                }
                m0 = nm0; m1 = nm1;
            }

            #pragma unroll
            for (int nf = 0; nf < 8; nf++) {
                s[nf][0] = ex2(s[nf][0] - m0);
                s[nf][1] = ex2(s[nf][1] - m0);
                s[nf][2] = ex2(s[nf][2] - m1);
                s[nf][3] = ex2(s[nf][3] - m1);
                l0 += s[nf][0] + s[nf][1];
                l1 += s[nf][2] + s[nf][3];
            }

            unsigned ap[4][4];
            #pragma unroll
            for (int ks = 0; ks < 4; ks++) {
                ap[ks][0] = f2h2(s[2 * ks][0],     s[2 * ks][1]);
                ap[ks][1] = f2h2(s[2 * ks][2],     s[2 * ks][3]);
                ap[ks][2] = f2h2(s[2 * ks + 1][0], s[2 * ks + 1][1]);
                ap[ks][3] = f2h2(s[2 * ks + 1][2], s[2 * ks + 1][3]);
            }

            #pragma unroll
            for (int ks = 0; ks < 4; ks++) {
                unsigned bv[4][4];
                #pragma unroll
                for (int np = 0; np < 4; np++) {
                    const int rowV = ks * 16 + (mat & 1) * 8 + mi;
                    const int ch   = 2 * np + (mat >> 1);
                    ldsm4t(bv[np], sV + (rowV * 8 + (ch ^ (rowV & 7))) * 16);
                }
                #pragma unroll
                for (int nf = 0; nf < 8; nf++)
                    mma16816(o[nf], ap[ks],
                             bv[nf >> 1][(nf & 1) * 2], bv[nf >> 1][(nf & 1) * 2 + 1]);
            }
        }
        __syncthreads();
    }

    #pragma unroll
    for (int off = 1; off <= 2; off <<= 1) {
        l0 += __shfl_xor_sync(0xffffffffu, l0, off);
        l1 += __shfl_xor_sync(0xffffffffu, l1, off);
    }
    const float inv0 = 1.f / l0;
    const float inv1 = 1.f / l1;

    const int row0 = b * NN + qt * 128 + w * 16 + r;
    #pragma unroll
    for (int nf = 0; nf < 8; nf++) {
        const int col = h * DD + nf * 8 + 2 * q;
        *(__half2*)&out[(size_t)row0 * CC + col] =
            __floats2half2_rn(o[nf][0] * inv0, o[nf][1] * inv0);
        *(__half2*)&out[(size_t)(row0 + 8) * CC + col] =
            __floats2half2_rn(o[nf][2] * inv1, o[nf][3] * inv1);
    }
}

// ---------------------------------------------------------------------------
// Launch
// ---------------------------------------------------------------------------
extern "C" void kernel_launch(void* const* d_in, const int* in_sizes, int n_in,
                              void* d_out, int out_size)
{
    const float* x      = (const float*)d_in[0];
    const float* amask  = (const float*)d_in[1];
    const float* W_qkv  = (const float*)d_in[2];
    const float* b_qkv  = (const float*)d_in[3];
    const float* W_proj = (const float*)d_in[4];
    const float* b_proj = (const float*)d_in[5];
    float* out = (float*)d_out;

    __half *x_h, *wqkv_t, *wproj_t, *qkv_h, *att_h;
    cudaGetSymbolAddress((void**)&x_h,     g_x_h);
    cudaGetSymbolAddress((void**)&wqkv_t,  g_wqkv_t);
    cudaGetSymbolAddress((void**)&wproj_t, g_wproj_t);
    cudaGetSymbolAddress((void**)&qkv_h,   g_qkv_h);
    cudaGetSymbolAddress((void**)&att_h,   g_att_h);

    static bool attr_set = false;
    if (!attr_set) {
        cudaFuncSetAttribute(gemm_f16_kernel<__half>,
                             cudaFuncAttributeMaxDynamicSharedMemorySize, GEMM_SMEM);
        cudaFuncSetAttribute(gemm_f16_kernel<float>,
                             cudaFuncAttributeMaxDynamicSharedMemorySize, GEMM_SMEM);
        cudaFuncSetAttribute(attn_f16_kernel,
                             cudaFuncAttributeMaxDynamicSharedMemorySize, AT_SMEM);
        attr_set = true;
    }

    // 0) fused conversions (x cvt + both weight transposes)
    prep_kernel<<<PREP_BLOCKS, 256>>>(x, x_h, W_qkv, wqkv_t, W_proj, wproj_t);

    // 1) QKV projection (fp16 out)
    {
        dim3 grid(QKV_COLS / 128, M_ROWS / 128);
        gemm_f16_kernel<__half><<<grid, 256, GEMM_SMEM>>>(
            x_h, wqkv_t, b_qkv, qkv_h, M_ROWS, CC, QKV_COLS);
    }
    // 2) Attention (fp16 out)
    {
        dim3 grid(BB * HH, NN / 128);
        attn_f16_kernel<<<grid, 256, AT_SMEM>>>(qkv_h, amask, att_h);
    }
    // 3) Output projection (fp32 out)
    {
        dim3 grid(CC / 128, M_ROWS / 128);
        gemm_f16_kernel<float><<<grid, 256, GEMM_SMEM>>>(
            att_h, wproj_t, b_proj, out, M_ROWS, CC, CC);
    }
}

// round 11
// speedup vs baseline: 1.2458x; 1.0088x over previous
#include <cuda_runtime.h>
#include <cuda_fp16.h>
#include <cstdint>

#define BB 8
#define NN 1024
#define CC 768
#define HH 12
#define DD 64
#define M_ROWS (BB * NN)        // 8192
#define QKV_COLS (3 * CC)       // 2304
#define ATT_SCALE 0.125f
#define LOG2E 1.4426950408889634f

// Scratch (device globals: allocation-free)
__device__ __half g_x_h[(size_t)M_ROWS * CC];
__device__ __half g_wqkv_t[(size_t)QKV_COLS * CC];   // [2304][768] K-major
__device__ __half g_wproj_t[(size_t)CC * CC];        // [768][768]  K-major
__device__ __half g_qkv_h[(size_t)M_ROWS * QKV_COLS];
__device__ __half g_att_h[(size_t)M_ROWS * CC];

// ---------------------------------------------------------------------------
// PTX helpers
// ---------------------------------------------------------------------------
__device__ __forceinline__ unsigned sptr(const void* p) {
    return (unsigned)__cvta_generic_to_shared(p);
}
__device__ __forceinline__ void cp16(unsigned s, const void* g) {
    asm volatile("cp.async.cg.shared.global [%0], [%1], 16;\n" :: "r"(s), "l"(g));
}
__device__ __forceinline__ void cp_commit() {
    asm volatile("cp.async.commit_group;\n");
}
template <int N>
__device__ __forceinline__ void cp_wait() {
    asm volatile("cp.async.wait_group %0;\n" :: "n"(N));
}
__device__ __forceinline__ void ldsm4(unsigned r[4], unsigned a) {
    asm volatile("ldmatrix.sync.aligned.m8n8.x4.shared.b16 {%0,%1,%2,%3}, [%4];\n"
                 : "=r"(r[0]), "=r"(r[1]), "=r"(r[2]), "=r"(r[3]) : "r"(a));
}
__device__ __forceinline__ void ldsm4t(unsigned r[4], unsigned a) {
    asm volatile("ldmatrix.sync.aligned.m8n8.x4.trans.shared.b16 {%0,%1,%2,%3}, [%4];\n"
                 : "=r"(r[0]), "=r"(r[1]), "=r"(r[2]), "=r"(r[3]) : "r"(a));
}
__device__ __forceinline__ void mma16816(float c[4], const unsigned a[4],
                                         unsigned b0, unsigned b1) {
    asm volatile(
        "mma.sync.aligned.m16n8k16.row.col.f32.f16.f16.f32 "
        "{%0,%1,%2,%3},{%4,%5,%6,%7},{%8,%9},{%0,%1,%2,%3};\n"
        : "+f"(c[0]), "+f"(c[1]), "+f"(c[2]), "+f"(c[3])
        : "r"(a[0]), "r"(a[1]), "r"(a[2]), "r"(a[3]), "r"(b0), "r"(b1));
}
__device__ __forceinline__ unsigned f2h2(float lo, float hi) {
    __half2 h = __floats2half2_rn(lo, hi);
    return *(unsigned*)&h;
}
__device__ __forceinline__ float ex2(float x) {
    float r;
    asm("ex2.approx.f32 %0, %1;" : "=f"(r) : "f"(x));
    return r;
}
__device__ __forceinline__ void store2(__half* p, float x, float y) {
    *(__half2*)p = __floats2half2_rn(x, y);
}
__device__ __forceinline__ void store2(float* p, float x, float y) {
    *(float2*)p = make_float2(x, y);
}

// ---------------------------------------------------------------------------
// fused prep: x f32->f16 + both weight transposes, one launch.
// ---------------------------------------------------------------------------
#define CVT_B 6144
#define TQ_BX (QKV_COLS / 32)
#define TQ_B  (TQ_BX * (CC / 32))
#define TP_BX (CC / 32)
#define TP_B  (TP_BX * (CC / 32))
#define PREP_BLOCKS (CVT_B + TQ_B + TP_B)

__global__ __launch_bounds__(256) void prep_kernel(
    const float* __restrict__ x, __half* __restrict__ x_h,
    const float* __restrict__ Wq, __half* __restrict__ Wq_t,
    const float* __restrict__ Wp, __half* __restrict__ Wp_t)
{
    __shared__ float t[32][33];
    const int bid = blockIdx.x;
    const int tid = threadIdx.x;

    if (bid < CVT_B) {
        const int i = bid * 256 + tid;
        float4 v = ((const float4*)x)[i];
        __half2 h0 = __floats2half2_rn(v.x, v.y);
        __half2 h1 = __floats2half2_rn(v.z, v.w);
        ((uint2*)x_h)[i] = make_uint2(*(unsigned*)&h0, *(unsigned*)&h1);
        return;
    }

    const float* W; __half* Wt; int cols, bx, by;
    if (bid < CVT_B + TQ_B) {
        const int b2 = bid - CVT_B;
        W = Wq; Wt = Wq_t; cols = QKV_COLS;
        bx = b2 % TQ_BX; by = b2 / TQ_BX;
    } else {
        const int b2 = bid - CVT_B - TQ_B;
        W = Wp; Wt = Wp_t; cols = CC;
        bx = b2 % TP_BX; by = b2 / TP_BX;
    }
    const int tx = tid & 31, ty = tid >> 5;
    #pragma unroll
    for (int i = 0; i < 4; i++)
        t[ty + i * 8][tx] = W[(size_t)(by * 32 + ty + i * 8) * cols + bx * 32 + tx];
    __syncthreads();
    #pragma unroll
    for (int i = 0; i < 4; i++)
        Wt[(size_t)(bx * 32 + ty + i * 8) * CC + by * 32 + tx] =
            __float2half(t[tx][ty + i * 8]);
}

// ---------------------------------------------------------------------------
// fp16 tensor-core GEMM, templated stage count.
// NST=3: single-barrier loop (best for large balanced grids — QKV).
// NST=2: two-barrier loop (best for small grids with tail waves — proj).
// 128x128 tile, BK=64, 256 threads, 8 warps (4m x 2n), warp tile 32x64.
// smem rows: 128B = 8 chunks of 16B; swizzle c ^= row&7.
// ---------------------------------------------------------------------------
#define G_ASZ   16384
#define G_STAGE (2 * G_ASZ)
#define GEMM_SMEM3 (3 * G_STAGE)      // 96 KB
#define GEMM_SMEM2 (2 * G_STAGE)      // 64 KB

template <typename OutT, int NST>
__global__ __launch_bounds__(256, 2) void gemm_f16_kernel(
    const __half* __restrict__ A, const __half* __restrict__ Bt,
    const float* __restrict__ bias, OutT* __restrict__ C,
    int M, int Kdim, int Ncols)
{
    extern __shared__ char smem[];
    const uint32_t sb = sptr(smem);

    const int tid  = threadIdx.x;
    const int lane = tid & 31;
    const int wid  = tid >> 5;
    const int wm   = wid >> 1;
    const int wn   = wid & 1;
    const int r    = lane >> 2;
    const int q    = lane & 3;
    const int mat  = lane >> 3;
    const int mi   = lane & 7;

    const int rowBase = blockIdx.y * 128;
    const int colBase = blockIdx.x * 128;

    float acc[2][8][4];
    #pragma unroll
    for (int mb = 0; mb < 2; mb++)
        #pragma unroll
        for (int nf = 0; nf < 8; nf++)
            #pragma unroll
            for (int c = 0; c < 4; c++) acc[mb][nf][c] = 0.f;

    const int nt = Kdim >> 6;

    auto stage = [&](int buf, int k0) {
        const uint32_t base = sb + buf * G_STAGE;
        #pragma unroll
        for (int i = 0; i < 4; i++) {
            const int j   = i * 256 + tid;
            const int row = j >> 3;
            const int c   = j & 7;
            const uint32_t soff = row * 128 + ((c ^ (row & 7)) * 16);
            cp16(base + soff,
                 A + (size_t)(rowBase + row) * Kdim + k0 + c * 8);
            cp16(base + G_ASZ + soff,
                 Bt + (size_t)(colBase + row) * Kdim + k0 + c * 8);
        }
        cp_commit();
    };

    auto compute = [&](uint32_t bA, uint32_t bB) {
        #pragma unroll
        for (int ks = 0; ks < 4; ks++) {
            const int chb = 2 * ks + (mat >> 1);
            unsigned af[2][4];
            #pragma unroll
            for (int mb = 0; mb < 2; mb++) {
                const int rowA = wm * 32 + mb * 16 + (mat & 1) * 8 + mi;
                ldsm4(af[mb], bA + rowA * 128 + ((chb ^ (rowA & 7)) * 16));
            }
            unsigned bf[4][4];
            #pragma unroll
            for (int np = 0; np < 4; np++) {
                const int rowB = wn * 64 + np * 16 + (mat & 1) * 8 + mi;
                ldsm4(bf[np], bB + rowB * 128 + ((chb ^ (rowB & 7)) * 16));
            }
            #pragma unroll
            for (int mb = 0; mb < 2; mb++)
                #pragma unroll
                for (int nf = 0; nf < 8; nf++)
                    mma16816(acc[mb][nf], af[mb],
                             bf[nf >> 1][nf & 1], bf[nf >> 1][(nf & 1) + 2]);
        }
    };

    if constexpr (NST == 3) {
        stage(0, 0);
        stage(1, 64);
        int cur = 0;
        for (int it = 0; it < nt; it++) {
            if (it + 1 < nt) cp_wait<1>(); else cp_wait<0>();
            __syncthreads();
            if (it + 2 < nt) {
                int nb = cur + 2; if (nb >= 3) nb -= 3;
                stage(nb, (it + 2) * 64);
            }
            const uint32_t bA = sb + cur * G_STAGE;
            compute(bA, bA + G_ASZ);
            if (++cur == 3) cur = 0;
        }
    } else {
        stage(0, 0);
        for (int it = 0; it < nt; it++) {
            if (it + 1 < nt) { stage((it + 1) & 1, (it + 1) * 64); cp_wait<1>(); }
            else             { cp_wait<0>(); }
            __syncthreads();
            const uint32_t bA = sb + (it & 1) * G_STAGE;
            compute(bA, bA + G_ASZ);
            __syncthreads();
        }
    }

    #pragma unroll
    for (int mb = 0; mb < 2; mb++) {
        const int row0 = rowBase + wm * 32 + mb * 16 + r;
        #pragma unroll
        for (int nf = 0; nf < 8; nf++) {
            const int col = colBase + wn * 64 + nf * 8 + 2 * q;
            const float2 bv = *(const float2*)&bias[col];
            store2(&C[(size_t)row0 * Ncols + col],
                   acc[mb][nf][0] + bv.x, acc[mb][nf][1] + bv.y);
            store2(&C[(size_t)(row0 + 8) * Ncols + col],
                   acc[mb][nf][2] + bv.x, acc[mb][nf][3] + bv.y);
        }
    }
}

// ---------------------------------------------------------------------------
// fp16 flash attention (R8 config — unchanged).
// ---------------------------------------------------------------------------
#define AT_Q    0
#define AT_KV   16384
#define AT_M    81920
#define AT_P    86016
#define AT_SMEM (AT_P + 16)

__global__ __launch_bounds__(256, 2) void attn_f16_kernel(
    const __half* __restrict__ qkv, const float* __restrict__ mask,
    __half* __restrict__ out)
{
    extern __shared__ char smem[];
    const uint32_t sb  = sptr(smem);
    const uint32_t sQ  = sb + AT_Q;
    const uint32_t sKV = sb + AT_KV;
    float* Ms = (float*)(smem + AT_M);
    int* sP   = (int*)(smem + AT_P);

    const int bh = blockIdx.x;
    const int b  = bh / HH;
    const int h  = bh % HH;
    const int qt = blockIdx.y;

    const int tid  = threadIdx.x;
    const int lane = tid & 31;
    const int w    = tid >> 5;
    const int r    = lane >> 2;
    const int q    = lane & 3;
    const int mat  = lane >> 3;
    const int mi   = lane & 7;

    if (tid == 0) *sP = NN;

    #pragma unroll
    for (int i = 0; i < 4; i++) {
        const int j = tid + i * 256;
        const int row = j >> 3, c0 = j & 7;
        cp16(sQ + (row * 8 + (c0 ^ (row & 7))) * 16,
             qkv + (size_t)(b * NN + qt * 128 + row) * QKV_COLS + h * DD + c0 * 8);
    }
    cp_commit();

    auto stage_pair = [&](int bp, int kt0) {
        #pragma unroll
        for (int t = 0; t < 2; t++) {
            const int buf = bp * 2 + t;
            const int kt  = kt0 + t;
            #pragma unroll
            for (int i = 0; i < 4; i++) {
                const int j  = tid + i * 256;
                const int kv = j >> 9;
                const int jj = j & 511;
                const int row = jj >> 3, c0 = jj & 7;
                cp16(sKV + buf * 16384 + kv * 8192 +
                         (row * 8 + (c0 ^ (row & 7))) * 16,
                     qkv + (size_t)(b * NN + kt * 64 + row) * QKV_COLS +
                         (kv + 1) * CC + h * DD + c0 * 8);
            }
        }
        cp_commit();
    };

    stage_pair(0, 0);

    {
        float4 mv = ((const float4*)(mask + b * NN))[tid];
        mv.x *= LOG2E; mv.y *= LOG2E; mv.z *= LOG2E; mv.w *= LOG2E;
        ((float4*)Ms)[tid] = mv;
    }

    cp_wait<0>();
    __syncthreads();

    {
        int firstPad = NN;
        #pragma unroll
        for (int i = 0; i < 4; i++) {
            const int idx = tid * 4 + i;
            if (Ms[idx] < -1e8f) { firstPad = idx; break; }
        }
        if (firstPad < NN) atomicMin(sP, firstPad);
    }
    __syncthreads();
    const int ntk    = (*sP + 63) >> 6;
    const int npairs = (ntk + 1) >> 1;

    unsigned qf[4][4];
    #pragma unroll
    for (int ks = 0; ks < 4; ks++) {
        const int rowQ = w * 16 + (mat & 1) * 8 + mi;
        const int ch   = 2 * ks + (mat >> 1);
        ldsm4(qf[ks], sQ + (rowQ * 8 + (ch ^ (rowQ & 7))) * 16);
    }

    float o[8][4];
    #pragma unroll
    for (int nf = 0; nf < 8; nf++)
        #pragma unroll
        for (int c = 0; c < 4; c++) o[nf][c] = 0.f;
    float m0 = -1e30f, m1 = -1e30f, l0 = 0.f, l1 = 0.f;

    const float SC2 = ATT_SCALE * LOG2E;

    for (int p = 0; p < npairs; p++) {
        if (p + 1 < npairs) { stage_pair((p + 1) & 1, (p + 1) * 2); cp_wait<1>(); }
        else                { cp_wait<0>(); }
        __syncthreads();

        const uint32_t pairBase = sKV + ((p & 1) * 2) * 16384;

        #pragma unroll
        for (int t = 0; t < 2; t++) {
            const int kt = p * 2 + t;
            if (kt >= ntk) break;
            const uint32_t sK = pairBase + t * 16384;
            const uint32_t sV = sK + 8192;

            float s[8][4];
            #pragma unroll
            for (int nf = 0; nf < 8; nf++)
                #pragma unroll
                for (int c = 0; c < 4; c++) s[nf][c] = 0.f;

            #pragma unroll
            for (int ks = 0; ks < 4; ks++) {
                unsigned bk[4][4];
                #pragma unroll
                for (int np = 0; np < 4; np++) {
                    const int rowK = np * 16 + (mat & 1) * 8 + mi;
                    const int ch   = 2 * ks + (mat >> 1);
                    ldsm4(bk[np], sK + (rowK * 8 + (ch ^ (rowK & 7))) * 16);
                }
                #pragma unroll
                for (int nf = 0; nf < 8; nf++)
                    mma16816(s[nf], qf[ks],
                             bk[nf >> 1][nf & 1], bk[nf >> 1][(nf & 1) + 2]);
            }

            float tmax0 = -1e30f, tmax1 = -1e30f;
            #pragma unroll
            for (int nf = 0; nf < 8; nf++) {
                const int col = kt * 64 + nf * 8 + 2 * q;
                const float2 mv = *(const float2*)&Ms[col];
                s[nf][0] = s[nf][0] * SC2 + mv.x;
                s[nf][1] = s[nf][1] * SC2 + mv.y;
                s[nf][2] = s[nf][2] * SC2 + mv.x;
                s[nf][3] = s[nf][3] * SC2 + mv.y;
                tmax0 = fmaxf(tmax0, fmaxf(s[nf][0], s[nf][1]));
                tmax1 = fmaxf(tmax1, fmaxf(s[nf][2], s[nf][3]));
            }
            #pragma unroll
            for (int off = 1; off <= 2; off <<= 1) {
                tmax0 = fmaxf(tmax0, __shfl_xor_sync(0xffffffffu, tmax0, off));
                tmax1 = fmaxf(tmax1, __shfl_xor_sync(0xffffffffu, tmax1, off));
            }
            const float nm0 = fmaxf(m0, tmax0);
            const float nm1 = fmaxf(m1, tmax1);
            if (__any_sync(0xffffffffu, (nm0 > m0) | (nm1 > m1))) {
                const float cr0 = ex2(m0 - nm0);
                const float cr1 = ex2(m1 - nm1);
                l0 *= cr0; l1 *= cr1;
                #pragma unroll
                for (int nf = 0; nf < 8; nf++) {
                    o[nf][0] *= cr0; o[nf][1] *= cr0;
                    o[nf][2] *= cr1; o[nf][3] *= cr1;
                }
                m0 = nm0; m1 = nm1;
            }

            #pragma unroll
            for (int nf = 0; nf < 8; nf++) {
                s[nf][0] = ex2(s[nf][0] - m0);
                s[nf][1] = ex2(s[nf][1] - m0);
                s[nf][2] = ex2(s[nf][2] - m1);
                s[nf][3] = ex2(s[nf][3] - m1);
                l0 += s[nf][0] + s[nf][1];
                l1 += s[nf][2] + s[nf][3];
            }

            unsigned ap[4][4];
            #pragma unroll
            for (int ks = 0; ks < 4; ks++) {
                ap[ks][0] = f2h2(s[2 * ks][0],     s[2 * ks][1]);
                ap[ks][1] = f2h2(s[2 * ks][2],     s[2 * ks][3]);
                ap[ks][2] = f2h2(s[2 * ks + 1][0], s[2 * ks + 1][1]);
                ap[ks][3] = f2h2(s[2 * ks + 1][2], s[2 * ks + 1][3]);
            }

            #pragma unroll
            for (int ks = 0; ks < 4; ks++) {
                unsigned bv[4][4];
                #pragma unroll
                for (int np = 0; np < 4; np++) {
                    const int rowV = ks * 16 + (mat & 1) * 8 + mi;
                    const int ch   = 2 * np + (mat >> 1);
                    ldsm4t(bv[np], sV + (rowV * 8 + (ch ^ (rowV & 7))) * 16);
                }
                #pragma unroll
                for (int nf = 0; nf < 8; nf++)
                    mma16816(o[nf], ap[ks],
                             bv[nf >> 1][(nf & 1) * 2], bv[nf >> 1][(nf & 1) * 2 + 1]);
            }
        }
        __syncthreads();
    }

    #pragma unroll
    for (int off = 1; off <= 2; off <<= 1) {
        l0 += __shfl_xor_sync(0xffffffffu, l0, off);
        l1 += __shfl_xor_sync(0xffffffffu, l1, off);
    }
    const float inv0 = 1.f / l0;
    const float inv1 = 1.f / l1;

    const int row0 = b * NN + qt * 128 + w * 16 + r;
    #pragma unroll
    for (int nf = 0; nf < 8; nf++) {
        const int col = h * DD + nf * 8 + 2 * q;
        *(__half2*)&out[(size_t)row0 * CC + col] =
            __floats2half2_rn(o[nf][0] * inv0, o[nf][1] * inv0);
        *(__half2*)&out[(size_t)(row0 + 8) * CC + col] =
            __floats2half2_rn(o[nf][2] * inv1, o[nf][3] * inv1);
    }
}

// ---------------------------------------------------------------------------
// Launch
// ---------------------------------------------------------------------------
extern "C" void kernel_launch(void* const* d_in, const int* in_sizes, int n_in,
                              void* d_out, int out_size)
{
    const float* x      = (const float*)d_in[0];
    const float* amask  = (const float*)d_in[1];
    const float* W_qkv  = (const float*)d_in[2];
    const float* b_qkv  = (const float*)d_in[3];
    const float* W_proj = (const float*)d_in[4];
    const float* b_proj = (const float*)d_in[5];
    float* out = (float*)d_out;

    __half *x_h, *wqkv_t, *wproj_t, *qkv_h, *att_h;
    cudaGetSymbolAddress((void**)&x_h,     g_x_h);
    cudaGetSymbolAddress((void**)&wqkv_t,  g_wqkv_t);
    cudaGetSymbolAddress((void**)&wproj_t, g_wproj_t);
    cudaGetSymbolAddress((void**)&qkv_h,   g_qkv_h);
    cudaGetSymbolAddress((void**)&att_h,   g_att_h);

    static bool attr_set = false;
    if (!attr_set) {
        cudaFuncSetAttribute((const void*)gemm_f16_kernel<__half, 3>,
                             cudaFuncAttributeMaxDynamicSharedMemorySize, GEMM_SMEM3);
        cudaFuncSetAttribute((const void*)gemm_f16_kernel<float, 2>,
                             cudaFuncAttributeMaxDynamicSharedMemorySize, GEMM_SMEM2);
        cudaFuncSetAttribute((const void*)attn_f16_kernel,
                             cudaFuncAttributeMaxDynamicSharedMemorySize, AT_SMEM);
        attr_set = true;
    }

    // 0) fused conversions
    prep_kernel<<<PREP_BLOCKS, 256>>>(x, x_h, W_qkv, wqkv_t, W_proj, wproj_t);

    // 1) QKV projection (fp16 out) — 3-stage single-barrier (big grid)
    {
        dim3 grid(QKV_COLS / 128, M_ROWS / 128);
        gemm_f16_kernel<__half, 3><<<grid, 256, GEMM_SMEM3>>>(
            x_h, wqkv_t, b_qkv, qkv_h, M_ROWS, CC, QKV_COLS);
    }
    // 2) Attention (fp16 out)
    {
        dim3 grid(BB * HH, NN / 128);
        attn_f16_kernel<<<grid, 256, AT_SMEM>>>(qkv_h, amask, att_h);
    }
    // 3) Output projection (fp32 out) — 2-stage (small grid, tail-wave bound)
    {
        dim3 grid(CC / 128, M_ROWS / 128);
        gemm_f16_kernel<float, 2><<<grid, 256, GEMM_SMEM2>>>(
            att_h, wproj_t, b_proj, out, M_ROWS, CC, CC);
    }
}

// round 12
// speedup vs baseline: 1.2732x; 1.0220x over previous
#include <cuda_runtime.h>
#include <cuda_fp16.h>
#include <cstdint>

#define BB 8
#define NN 1024
#define CC 768
#define HH 12
#define DD 64
#define M_ROWS (BB * NN)        // 8192
#define QKV_COLS (3 * CC)       // 2304
#define ATT_SCALE 0.125f
#define LOG2E 1.4426950408889634f

// Scratch (device globals: allocation-free)
__device__ __half g_x_h[(size_t)M_ROWS * CC];
__device__ __half g_wqkv_t[(size_t)QKV_COLS * CC];   // [2304][768] K-major
__device__ __half g_wproj_t[(size_t)CC * CC];        // [768][768]  K-major
__device__ __half g_qkv_h[(size_t)M_ROWS * QKV_COLS];
__device__ __half g_att_h[(size_t)M_ROWS * CC];

// ---------------------------------------------------------------------------
// PTX helpers
// ---------------------------------------------------------------------------
__device__ __forceinline__ unsigned sptr(const void* p) {
    return (unsigned)__cvta_generic_to_shared(p);
}
__device__ __forceinline__ void cp16(unsigned s, const void* g) {
    asm volatile("cp.async.cg.shared.global [%0], [%1], 16;\n" :: "r"(s), "l"(g));
}
__device__ __forceinline__ void cp_commit() {
    asm volatile("cp.async.commit_group;\n");
}
template <int N>
__device__ __forceinline__ void cp_wait() {
    asm volatile("cp.async.wait_group %0;\n" :: "n"(N));
}
__device__ __forceinline__ void ldsm4(unsigned r[4], unsigned a) {
    asm volatile("ldmatrix.sync.aligned.m8n8.x4.shared.b16 {%0,%1,%2,%3}, [%4];\n"
                 : "=r"(r[0]), "=r"(r[1]), "=r"(r[2]), "=r"(r[3]) : "r"(a));
}
__device__ __forceinline__ void ldsm4t(unsigned r[4], unsigned a) {
    asm volatile("ldmatrix.sync.aligned.m8n8.x4.trans.shared.b16 {%0,%1,%2,%3}, [%4];\n"
                 : "=r"(r[0]), "=r"(r[1]), "=r"(r[2]), "=r"(r[3]) : "r"(a));
}
__device__ __forceinline__ void mma16816(float c[4], const unsigned a[4],
                                         unsigned b0, unsigned b1) {
    asm volatile(
        "mma.sync.aligned.m16n8k16.row.col.f32.f16.f16.f32 "
        "{%0,%1,%2,%3},{%4,%5,%6,%7},{%8,%9},{%0,%1,%2,%3};\n"
        : "+f"(c[0]), "+f"(c[1]), "+f"(c[2]), "+f"(c[3])
        : "r"(a[0]), "r"(a[1]), "r"(a[2]), "r"(a[3]), "r"(b0), "r"(b1));
}
__device__ __forceinline__ float ex2(float x) {
    float r;
    asm("ex2.approx.f32 %0, %1;" : "=f"(r) : "f"(x));
    return r;
}
// pack two f32 into f16x2 (lo in low half)
__device__ __forceinline__ unsigned cvt_h2(float lo, float hi) {
    unsigned d;
    asm("cvt.rn.f16x2.f32 %0, %1, %2;" : "=r"(d) : "f"(hi), "f"(lo));
    return d;
}
// paired fp16 exp2
__device__ __forceinline__ unsigned ex2_h2(unsigned a) {
    unsigned d;
    asm("ex2.approx.f16x2 %0, %1;" : "=r"(d) : "r"(a));
    return d;
}
__device__ __forceinline__ unsigned hadd2(unsigned a, unsigned b) {
    unsigned d;
    asm("add.rn.f16x2 %0, %1, %2;" : "=r"(d) : "r"(a), "r"(b));
    return d;
}
__device__ __forceinline__ void store2(__half* p, float x, float y) {
    *(__half2*)p = __floats2half2_rn(x, y);
}
__device__ __forceinline__ void store2(float* p, float x, float y) {
    *(float2*)p = make_float2(x, y);
}

// ---------------------------------------------------------------------------
// fused prep: x f32->f16 + both weight transposes, one launch.
// ---------------------------------------------------------------------------
#define CVT_B 6144
#define TQ_BX (QKV_COLS / 32)
#define TQ_B  (TQ_BX * (CC / 32))
#define TP_BX (CC / 32)
#define TP_B  (TP_BX * (CC / 32))
#define PREP_BLOCKS (CVT_B + TQ_B + TP_B)

__global__ __launch_bounds__(256) void prep_kernel(
    const float* __restrict__ x, __half* __restrict__ x_h,
    const float* __restrict__ Wq, __half* __restrict__ Wq_t,
    const float* __restrict__ Wp, __half* __restrict__ Wp_t)
{
    __shared__ float t[32][33];
    const int bid = blockIdx.x;
    const int tid = threadIdx.x;

    if (bid < CVT_B) {
        const int i = bid * 256 + tid;
        float4 v = ((const float4*)x)[i];
        __half2 h0 = __floats2half2_rn(v.x, v.y);
        __half2 h1 = __floats2half2_rn(v.z, v.w);
        ((uint2*)x_h)[i] = make_uint2(*(unsigned*)&h0, *(unsigned*)&h1);
        return;
    }

    const float* W; __half* Wt; int cols, bx, by;
    if (bid < CVT_B + TQ_B) {
        const int b2 = bid - CVT_B;
        W = Wq; Wt = Wq_t; cols = QKV_COLS;
        bx = b2 % TQ_BX; by = b2 / TQ_BX;
    } else {
        const int b2 = bid - CVT_B - TQ_B;
        W = Wp; Wt = Wp_t; cols = CC;
        bx = b2 % TP_BX; by = b2 / TP_BX;
    }
    const int tx = tid & 31, ty = tid >> 5;
    #pragma unroll
    for (int i = 0; i < 4; i++)
        t[ty + i * 8][tx] = W[(size_t)(by * 32 + ty + i * 8) * cols + bx * 32 + tx];
    __syncthreads();
    #pragma unroll
    for (int i = 0; i < 4; i++)
        Wt[(size_t)(bx * 32 + ty + i * 8) * CC + by * 32 + tx] =
            __float2half(t[tx][ty + i * 8]);
}

// ---------------------------------------------------------------------------
// fp16 tensor-core GEMM, templated stage count (R10 config — frozen).
// ---------------------------------------------------------------------------
#define G_ASZ   16384
#define G_STAGE (2 * G_ASZ)
#define GEMM_SMEM3 (3 * G_STAGE)
#define GEMM_SMEM2 (2 * G_STAGE)

template <typename OutT, int NST>
__global__ __launch_bounds__(256, 2) void gemm_f16_kernel(
    const __half* __restrict__ A, const __half* __restrict__ Bt,
    const float* __restrict__ bias, OutT* __restrict__ C,
    int M, int Kdim, int Ncols)
{
    extern __shared__ char smem[];
    const uint32_t sb = sptr(smem);

    const int tid  = threadIdx.x;
    const int lane = tid & 31;
    const int wid  = tid >> 5;
    const int wm   = wid >> 1;
    const int wn   = wid & 1;
    const int r    = lane >> 2;
    const int q    = lane & 3;
    const int mat  = lane >> 3;
    const int mi   = lane & 7;

    const int rowBase = blockIdx.y * 128;
    const int colBase = blockIdx.x * 128;

    float acc[2][8][4];
    #pragma unroll
    for (int mb = 0; mb < 2; mb++)
        #pragma unroll
        for (int nf = 0; nf < 8; nf++)
            #pragma unroll
            for (int c = 0; c < 4; c++) acc[mb][nf][c] = 0.f;

    const int nt = Kdim >> 6;

    auto stage = [&](int buf, int k0) {
        const uint32_t base = sb + buf * G_STAGE;
        #pragma unroll
        for (int i = 0; i < 4; i++) {
            const int j   = i * 256 + tid;
            const int row = j >> 3;
            const int c   = j & 7;
            const uint32_t soff = row * 128 + ((c ^ (row & 7)) * 16);
            cp16(base + soff,
                 A + (size_t)(rowBase + row) * Kdim + k0 + c * 8);
            cp16(base + G_ASZ + soff,
                 Bt + (size_t)(colBase + row) * Kdim + k0 + c * 8);
        }
        cp_commit();
    };

    auto compute = [&](uint32_t bA, uint32_t bB) {
        #pragma unroll
        for (int ks = 0; ks < 4; ks++) {
            const int chb = 2 * ks + (mat >> 1);
            unsigned af[2][4];
            #pragma unroll
            for (int mb = 0; mb < 2; mb++) {
                const int rowA = wm * 32 + mb * 16 + (mat & 1) * 8 + mi;
                ldsm4(af[mb], bA + rowA * 128 + ((chb ^ (rowA & 7)) * 16));
            }
            unsigned bf[4][4];
            #pragma unroll
            for (int np = 0; np < 4; np++) {
                const int rowB = wn * 64 + np * 16 + (mat & 1) * 8 + mi;
                ldsm4(bf[np], bB + rowB * 128 + ((chb ^ (rowB & 7)) * 16));
            }
            #pragma unroll
            for (int mb = 0; mb < 2; mb++)
                #pragma unroll
                for (int nf = 0; nf < 8; nf++)
                    mma16816(acc[mb][nf], af[mb],
                             bf[nf >> 1][nf & 1], bf[nf >> 1][(nf & 1) + 2]);
        }
    };

    if constexpr (NST == 3) {
        stage(0, 0);
        stage(1, 64);
        int cur = 0;
        for (int it = 0; it < nt; it++) {
            if (it + 1 < nt) cp_wait<1>(); else cp_wait<0>();
            __syncthreads();
            if (it + 2 < nt) {
                int nb = cur + 2; if (nb >= 3) nb -= 3;
                stage(nb, (it + 2) * 64);
            }
            const uint32_t bA = sb + cur * G_STAGE;
            compute(bA, bA + G_ASZ);
            if (++cur == 3) cur = 0;
        }
    } else {
        stage(0, 0);
        for (int it = 0; it < nt; it++) {
            if (it + 1 < nt) { stage((it + 1) & 1, (it + 1) * 64); cp_wait<1>(); }
            else             { cp_wait<0>(); }
            __syncthreads();
            const uint32_t bA = sb + (it & 1) * G_STAGE;
            compute(bA, bA + G_ASZ);
            __syncthreads();
        }
    }

    #pragma unroll
    for (int mb = 0; mb < 2; mb++) {
        const int row0 = rowBase + wm * 32 + mb * 16 + r;
        #pragma unroll
        for (int nf = 0; nf < 8; nf++) {
            const int col = colBase + wn * 64 + nf * 8 + 2 * q;
            const float2 bv = *(const float2*)&bias[col];
            store2(&C[(size_t)row0 * Ncols + col],
                   acc[mb][nf][0] + bv.x, acc[mb][nf][1] + bv.y);
            store2(&C[(size_t)(row0 + 8) * Ncols + col],
                   acc[mb][nf][2] + bv.x, acc[mb][nf][3] + bv.y);
        }
    }
}

// ---------------------------------------------------------------------------
// fp16 flash attention. R11: softmax exp via ex2.approx.f16x2 (paired fp16
// exp; halves MUFU load, removes f2h2 cvts — P lands in fp16 anyway).
// l accumulated via HADD2 tree per tile. Rest = R8 config.
// ---------------------------------------------------------------------------
#define AT_Q    0
#define AT_KV   16384
#define AT_M    81920
#define AT_P    86016
#define AT_SMEM (AT_P + 16)

__global__ __launch_bounds__(256, 2) void attn_f16_kernel(
    const __half* __restrict__ qkv, const float* __restrict__ mask,
    __half* __restrict__ out)
{
    extern __shared__ char smem[];
    const uint32_t sb  = sptr(smem);
    const uint32_t sQ  = sb + AT_Q;
    const uint32_t sKV = sb + AT_KV;
    float* Ms = (float*)(smem + AT_M);
    int* sP   = (int*)(smem + AT_P);

    const int bh = blockIdx.x;
    const int b  = bh / HH;
    const int h  = bh % HH;
    const int qt = blockIdx.y;

    const int tid  = threadIdx.x;
    const int lane = tid & 31;
    const int w    = tid >> 5;
    const int r    = lane >> 2;
    const int q    = lane & 3;
    const int mat  = lane >> 3;
    const int mi   = lane & 7;

    if (tid == 0) *sP = NN;

    #pragma unroll
    for (int i = 0; i < 4; i++) {
        const int j = tid + i * 256;
        const int row = j >> 3, c0 = j & 7;
        cp16(sQ + (row * 8 + (c0 ^ (row & 7))) * 16,
             qkv + (size_t)(b * NN + qt * 128 + row) * QKV_COLS + h * DD + c0 * 8);
    }
    cp_commit();

    auto stage_pair = [&](int bp, int kt0) {
        #pragma unroll
        for (int t = 0; t < 2; t++) {
            const int buf = bp * 2 + t;
            const int kt  = kt0 + t;
            #pragma unroll
            for (int i = 0; i < 4; i++) {
                const int j  = tid + i * 256;
                const int kv = j >> 9;
                const int jj = j & 511;
                const int row = jj >> 3, c0 = jj & 7;
                cp16(sKV + buf * 16384 + kv * 8192 +
                         (row * 8 + (c0 ^ (row & 7))) * 16,
                     qkv + (size_t)(b * NN + kt * 64 + row) * QKV_COLS +
                         (kv + 1) * CC + h * DD + c0 * 8);
            }
        }
        cp_commit();
    };

    stage_pair(0, 0);

    {
        float4 mv = ((const float4*)(mask + b * NN))[tid];
        mv.x *= LOG2E; mv.y *= LOG2E; mv.z *= LOG2E; mv.w *= LOG2E;
        ((float4*)Ms)[tid] = mv;
    }

    cp_wait<0>();
    __syncthreads();

    {
        int firstPad = NN;
        #pragma unroll
        for (int i = 0; i < 4; i++) {
            const int idx = tid * 4 + i;
            if (Ms[idx] < -1e8f) { firstPad = idx; break; }
        }
        if (firstPad < NN) atomicMin(sP, firstPad);
    }
    __syncthreads();
    const int ntk    = (*sP + 63) >> 6;
    const int npairs = (ntk + 1) >> 1;

    unsigned qf[4][4];
    #pragma unroll
    for (int ks = 0; ks < 4; ks++) {
        const int rowQ = w * 16 + (mat & 1) * 8 + mi;
        const int ch   = 2 * ks + (mat >> 1);
        ldsm4(qf[ks], sQ + (rowQ * 8 + (ch ^ (rowQ & 7))) * 16);
    }

    float o[8][4];
    #pragma unroll
    for (int nf = 0; nf < 8; nf++)
        #pragma unroll
        for (int c = 0; c < 4; c++) o[nf][c] = 0.f;
    float m0 = -1e30f, m1 = -1e30f, l0 = 0.f, l1 = 0.f;

    const float SC2 = ATT_SCALE * LOG2E;

    for (int p = 0; p < npairs; p++) {
        if (p + 1 < npairs) { stage_pair((p + 1) & 1, (p + 1) * 2); cp_wait<1>(); }
        else                { cp_wait<0>(); }
        __syncthreads();

        const uint32_t pairBase = sKV + ((p & 1) * 2) * 16384;

        #pragma unroll
        for (int t = 0; t < 2; t++) {
            const int kt = p * 2 + t;
            if (kt >= ntk) break;
            const uint32_t sK = pairBase + t * 16384;
            const uint32_t sV = sK + 8192;

            float s[8][4];
            #pragma unroll
            for (int nf = 0; nf < 8; nf++)
                #pragma unroll
                for (int c = 0; c < 4; c++) s[nf][c] = 0.f;

            #pragma unroll
            for (int ks = 0; ks < 4; ks++) {
                unsigned bk[4][4];
                #pragma unroll
                for (int np = 0; np < 4; np++) {
                    const int rowK = np * 16 + (mat & 1) * 8 + mi;
                    const int ch   = 2 * ks + (mat >> 1);
                    ldsm4(bk[np], sK + (rowK * 8 + (ch ^ (rowK & 7))) * 16);
                }
                #pragma unroll
                for (int nf = 0; nf < 8; nf++)
                    mma16816(s[nf], qf[ks],
                             bk[nf >> 1][nf & 1], bk[nf >> 1][(nf & 1) + 2]);
            }

            float tmax0 = -1e30f, tmax1 = -1e30f;
            #pragma unroll
            for (int nf = 0; nf < 8; nf++) {
                const int col = kt * 64 + nf * 8 + 2 * q;
                const float2 mv = *(const float2*)&Ms[col];
                s[nf][0] = s[nf][0] * SC2 + mv.x;
                s[nf][1] = s[nf][1] * SC2 + mv.y;
                s[nf][2] = s[nf][2] * SC2 + mv.x;
                s[nf][3] = s[nf][3] * SC2 + mv.y;
                tmax0 = fmaxf(tmax0, fmaxf(s[nf][0], s[nf][1]));
                tmax1 = fmaxf(tmax1, fmaxf(s[nf][2], s[nf][3]));
            }
            #pragma unroll
            for (int off = 1; off <= 2; off <<= 1) {
                tmax0 = fmaxf(tmax0, __shfl_xor_sync(0xffffffffu, tmax0, off));
                tmax1 = fmaxf(tmax1, __shfl_xor_sync(0xffffffffu, tmax1, off));
            }
            const float nm0 = fmaxf(m0, tmax0);
            const float nm1 = fmaxf(m1, tmax1);
            if (__any_sync(0xffffffffu, (nm0 > m0) | (nm1 > m1))) {
                const float cr0 = ex2(m0 - nm0);
                const float cr1 = ex2(m1 - nm1);
                l0 *= cr0; l1 *= cr1;
                #pragma unroll
                for (int nf = 0; nf < 8; nf++) {
                    o[nf][0] *= cr0; o[nf][1] *= cr0;
                    o[nf][2] *= cr1; o[nf][3] *= cr1;
                }
                m0 = nm0; m1 = nm1;
            }

            // ---- paired fp16 exp: P fragments directly, l via HADD2 ----
            unsigned ph[8][2];
            #pragma unroll
            for (int nf = 0; nf < 8; nf++) {
                ph[nf][0] = ex2_h2(cvt_h2(s[nf][0] - m0, s[nf][1] - m0));
                ph[nf][1] = ex2_h2(cvt_h2(s[nf][2] - m1, s[nf][3] - m1));
            }
            {
                unsigned lh0 = ph[0][0], lh1 = ph[0][1];
                #pragma unroll
                for (int nf = 1; nf < 8; nf++) {
                    lh0 = hadd2(lh0, ph[nf][0]);
                    lh1 = hadd2(lh1, ph[nf][1]);
                }
                const __half2 h0 = *(__half2*)&lh0;
                const __half2 h1 = *(__half2*)&lh1;
                l0 += __low2float(h0) + __high2float(h0);
                l1 += __low2float(h1) + __high2float(h1);
            }

            unsigned ap[4][4];
            #pragma unroll
            for (int ks = 0; ks < 4; ks++) {
                ap[ks][0] = ph[2 * ks][0];
                ap[ks][1] = ph[2 * ks][1];
                ap[ks][2] = ph[2 * ks + 1][0];
                ap[ks][3] = ph[2 * ks + 1][1];
            }

            #pragma unroll
            for (int ks = 0; ks < 4; ks++) {
                unsigned bv[4][4];
                #pragma unroll
                for (int np = 0; np < 4; np++) {
                    const int rowV = ks * 16 + (mat & 1) * 8 + mi;
                    const int ch   = 2 * np + (mat >> 1);
                    ldsm4t(bv[np], sV + (rowV * 8 + (ch ^ (rowV & 7))) * 16);
                }
                #pragma unroll
                for (int nf = 0; nf < 8; nf++)
                    mma16816(o[nf], ap[ks],
                             bv[nf >> 1][(nf & 1) * 2], bv[nf >> 1][(nf & 1) * 2 + 1]);
            }
        }
        __syncthreads();
    }

    #pragma unroll
    for (int off = 1; off <= 2; off <<= 1) {
        l0 += __shfl_xor_sync(0xffffffffu, l0, off);
        l1 += __shfl_xor_sync(0xffffffffu, l1, off);
    }
    const float inv0 = 1.f / l0;
    const float inv1 = 1.f / l1;

    const int row0 = b * NN + qt * 128 + w * 16 + r;
    #pragma unroll
    for (int nf = 0; nf < 8; nf++) {
        const int col = h * DD + nf * 8 + 2 * q;
        *(__half2*)&out[(size_t)row0 * CC + col] =
            __floats2half2_rn(o[nf][0] * inv0, o[nf][1] * inv0);
        *(__half2*)&out[(size_t)(row0 + 8) * CC + col] =
            __floats2half2_rn(o[nf][2] * inv1, o[nf][3] * inv1);
    }
}

// ---------------------------------------------------------------------------
// Launch
// ---------------------------------------------------------------------------
extern "C" void kernel_launch(void* const* d_in, const int* in_sizes, int n_in,
                              void* d_out, int out_size)
{
    const float* x      = (const float*)d_in[0];
    const float* amask  = (const float*)d_in[1];
    const float* W_qkv  = (const float*)d_in[2];
    const float* b_qkv  = (const float*)d_in[3];
    const float* W_proj = (const float*)d_in[4];
    const float* b_proj = (const float*)d_in[5];
    float* out = (float*)d_out;

    __half *x_h, *wqkv_t, *wproj_t, *qkv_h, *att_h;
    cudaGetSymbolAddress((void**)&x_h,     g_x_h);
    cudaGetSymbolAddress((void**)&wqkv_t,  g_wqkv_t);
    cudaGetSymbolAddress((void**)&wproj_t, g_wproj_t);
    cudaGetSymbolAddress((void**)&qkv_h,   g_qkv_h);
    cudaGetSymbolAddress((void**)&att_h,   g_att_h);

    static bool attr_set = false;
    if (!attr_set) {
        cudaFuncSetAttribute((const void*)gemm_f16_kernel<__half, 3>,
                             cudaFuncAttributeMaxDynamicSharedMemorySize, GEMM_SMEM3);
        cudaFuncSetAttribute((const void*)gemm_f16_kernel<float, 2>,
                             cudaFuncAttributeMaxDynamicSharedMemorySize, GEMM_SMEM2);
        cudaFuncSetAttribute((const void*)attn_f16_kernel,
                             cudaFuncAttributeMaxDynamicSharedMemorySize, AT_SMEM);
        attr_set = true;
    }

    // 0) fused conversions
    prep_kernel<<<PREP_BLOCKS, 256>>>(x, x_h, W_qkv, wqkv_t, W_proj, wproj_t);

    // 1) QKV projection (fp16 out) — 3-stage single-barrier
    {
        dim3 grid(QKV_COLS / 128, M_ROWS / 128);
        gemm_f16_kernel<__half, 3><<<grid, 256, GEMM_SMEM3>>>(
            x_h, wqkv_t, b_qkv, qkv_h, M_ROWS, CC, QKV_COLS);
    }
    // 2) Attention (fp16 out)
    {
        dim3 grid(BB * HH, NN / 128);
        attn_f16_kernel<<<grid, 256, AT_SMEM>>>(qkv_h, amask, att_h);
    }
    // 3) Output projection (fp32 out) — 2-stage
    {
        dim3 grid(CC / 128, M_ROWS / 128);
        gemm_f16_kernel<float, 2><<<grid, 256, GEMM_SMEM2>>>(
            att_h, wproj_t, b_proj, out, M_ROWS, CC, CC);
    }
}